// round 2
// baseline (speedup 1.0000x reference)
#include <cuda_runtime.h>
#include <cuda_bf16.h>

namespace {

constexpr int N  = 50000;
constexpr int E  = 1600000;
constexpr int IN = 512;
constexpr int H  = 128;
constexpr int C  = 2;
constexpr int G  = 8;

// Scratch (static device allocations — allowed; ~102 MB total)
__device__ float g_lin[(size_t)N * H];   // post-linear (no bias) for current layer
__device__ float g_hs [(size_t)N * H];   // row-scaled (h * dinv) — gather source
__device__ float g_t  [(size_t)N * H];   // scatter accumulator
__device__ float g_h  [(size_t)N * H];   // layer output (post relu)
__device__ float g_dinv[N];
__device__ float g_deg [N];
__device__ float g_pool[G * H];
__device__ float g_cnt [G];

__global__ void zero_kernel(float* __restrict__ p, int n) {
    int i = blockIdx.x * blockDim.x + threadIdx.x;
    if (i < n) p[i] = 0.0f;
}

__global__ void deg_kernel(const int* __restrict__ dst) {
    int e = blockIdx.x * blockDim.x + threadIdx.x;
    if (e < E) atomicAdd(&g_deg[dst[e]], 1.0f);
}

__global__ void dinv_kernel() {
    int i = blockIdx.x * blockDim.x + threadIdx.x;
    if (i < N) g_dinv[i] = rsqrtf(g_deg[i] + 1.0f);
}

// Classic 128x128 tile SGEMM, BK=8, 256 threads, 8x8 micro-tile.
// Writes lin = A@W and hs = lin * dinv[row] (fused epilogue).
template <int K>
__global__ void __launch_bounds__(256)
gemm_kernel(const float* __restrict__ A, const float* __restrict__ W,
            float* __restrict__ lin, float* __restrict__ hs) {
    __shared__ float As[8][128];
    __shared__ float Bs[8][128];

    const int tid = threadIdx.x;
    const int block_m = blockIdx.x * 128;
    const int ty = tid >> 4;       // 0..15 (row group)
    const int tx = tid & 15;       // 0..15 (col group)

    const int arow = tid >> 1;           // 0..127
    const int acol = (tid & 1) * 4;      // 0 or 4
    const int brow = tid >> 5;           // 0..7
    const int bcol = (tid & 31) * 4;     // 0..124

    float acc[8][8];
    #pragma unroll
    for (int i = 0; i < 8; i++)
        #pragma unroll
        for (int j = 0; j < 8; j++) acc[i][j] = 0.0f;

    const int m_a = block_m + arow;
    const bool a_ok = (m_a < N);
    const float4* aptr = reinterpret_cast<const float4*>(A + (size_t)m_a * K + acol);
    const float4* bptr = reinterpret_cast<const float4*>(W + (size_t)brow * H + bcol);

    for (int k0 = 0; k0 < K; k0 += 8) {
        float4 av = make_float4(0.f, 0.f, 0.f, 0.f);
        if (a_ok) av = aptr[k0 / 4];  // (m_a*K + k0 + acol)/4
        As[acol + 0][arow] = av.x;
        As[acol + 1][arow] = av.y;
        As[acol + 2][arow] = av.z;
        As[acol + 3][arow] = av.w;

        float4 bv = bptr[(size_t)k0 * H / 4];
        *reinterpret_cast<float4*>(&Bs[brow][bcol]) = bv;
        __syncthreads();

        #pragma unroll
        for (int k = 0; k < 8; k++) {
            float ra[8], rb[8];
            #pragma unroll
            for (int i = 0; i < 8; i++) ra[i] = As[k][ty * 8 + i];
            #pragma unroll
            for (int j = 0; j < 8; j++) rb[j] = Bs[k][tx * 8 + j];
            #pragma unroll
            for (int i = 0; i < 8; i++)
                #pragma unroll
                for (int j = 0; j < 8; j++)
                    acc[i][j] = fmaf(ra[i], rb[j], acc[i][j]);
        }
        __syncthreads();
    }

    #pragma unroll
    for (int i = 0; i < 8; i++) {
        int m = block_m + ty * 8 + i;
        if (m >= N) break;
        float di = g_dinv[m];
        #pragma unroll
        for (int j = 0; j < 8; j += 4) {
            float4 v = make_float4(acc[i][j], acc[i][j + 1], acc[i][j + 2], acc[i][j + 3]);
            *reinterpret_cast<float4*>(lin + (size_t)m * H + tx * 8 + j) = v;
            float4 s = make_float4(v.x * di, v.y * di, v.z * di, v.w * di);
            *reinterpret_cast<float4*>(hs + (size_t)m * H + tx * 8 + j) = s;
        }
    }
}

// One warp per edge: lane reads float4 of hs[src] row, red.v4 into t[dst] row.
__global__ void __launch_bounds__(256)
scatter_kernel(const int* __restrict__ src, const int* __restrict__ dst,
               const float* __restrict__ hs, float* __restrict__ t) {
    int w = (blockIdx.x * 256 + threadIdx.x) >> 5;
    if (w >= E) return;
    int lane = threadIdx.x & 31;
    int s = __ldg(src + w);
    int d = __ldg(dst + w);
    float4 v = *reinterpret_cast<const float4*>(hs + (size_t)s * H + lane * 4);
    float* p = t + (size_t)d * H + lane * 4;
    asm volatile("red.global.add.v4.f32 [%0], {%1,%2,%3,%4};"
                 :: "l"(p), "f"(v.x), "f"(v.y), "f"(v.z), "f"(v.w) : "memory");
}

// h = relu(dinv*t + lin*dinv^2 + b)
__global__ void epilogue_kernel(const float* __restrict__ lin, const float* __restrict__ t,
                                const float* __restrict__ b, float* __restrict__ hout) {
    int i = blockIdx.x * blockDim.x + threadIdx.x;   // float4 index
    if (i >= N * H / 4) return;
    int row = i >> 5;                 // / (H/4)
    int col4 = (i & 31) * 4;
    float di = g_dinv[row];
    float di2 = di * di;
    float4 tv = reinterpret_cast<const float4*>(t)[i];
    float4 lv = reinterpret_cast<const float4*>(lin)[i];
    float4 r;
    r.x = fmaxf(fmaf(di, tv.x, lv.x * di2) + b[col4 + 0], 0.f);
    r.y = fmaxf(fmaf(di, tv.y, lv.y * di2) + b[col4 + 1], 0.f);
    r.z = fmaxf(fmaf(di, tv.z, lv.z * di2) + b[col4 + 2], 0.f);
    r.w = fmaxf(fmaf(di, tv.w, lv.w * di2) + b[col4 + 3], 0.f);
    reinterpret_cast<float4*>(hout)[i] = r;
}

__global__ void __launch_bounds__(256)
pool_kernel(const int* __restrict__ batch, const float* __restrict__ h) {
    __shared__ float acc[G * H];
    __shared__ float cnt[G];
    int tid = threadIdx.x;
    for (int i = tid; i < G * H; i += 256) acc[i] = 0.f;
    if (tid < G) cnt[tid] = 0.f;
    __syncthreads();

    int nodes_per_block = (N + gridDim.x - 1) / gridDim.x;
    int n0 = blockIdx.x * nodes_per_block;
    int n1 = min(n0 + nodes_per_block, N);
    int warp = tid >> 5, lane = tid & 31;

    for (int n = n0 + warp; n < n1; n += 8) {
        int g = batch[n];
        #pragma unroll
        for (int j = 0; j < 4; j++) {
            float v = h[(size_t)n * H + lane + j * 32];
            atomicAdd(&acc[g * H + lane + j * 32], v);
        }
        if (lane == 0) atomicAdd(&cnt[g], 1.0f);
    }
    __syncthreads();

    for (int i = tid; i < G * H; i += 256)
        if (acc[i] != 0.f) atomicAdd(&g_pool[i], acc[i]);
    if (tid < G && cnt[tid] != 0.f) atomicAdd(&g_cnt[tid], cnt[tid]);
}

// out[g,c] = (pool[g,:] @ Wlin[:,c]) / max(cnt[g],1) + blin[c]
__global__ void head_kernel(const float* __restrict__ Wlin, const float* __restrict__ blin,
                            float* __restrict__ out) {
    int warp = threadIdx.x >> 5, lane = threadIdx.x & 31;
    if (warp >= G * C) return;
    int g = warp >> 1, c = warp & 1;
    float s = 0.f;
    for (int d = lane; d < H; d += 32)
        s += g_pool[g * H + d] * Wlin[d * C + c];
    #pragma unroll
    for (int o = 16; o; o >>= 1) s += __shfl_xor_sync(0xffffffff, s, o);
    if (lane == 0) out[g * C + c] = s / fmaxf(g_cnt[g], 1.0f) + blin[c];
}

} // namespace

extern "C" void kernel_launch(void* const* d_in, const int* in_sizes, int n_in,
                              void* d_out, int out_size) {
    const float* x    = (const float*)d_in[0];
    const int*   ei   = (const int*)  d_in[1];
    const int*   bat  = (const int*)  d_in[2];
    const float* W1   = (const float*)d_in[3];
    const float* b1   = (const float*)d_in[4];
    const float* W2   = (const float*)d_in[5];
    const float* b2   = (const float*)d_in[6];
    const float* Wlin = (const float*)d_in[7];
    const float* blin = (const float*)d_in[8];
    float* out = (float*)d_out;
    const int* src = ei;
    const int* dst = ei + E;

    float *p_lin, *p_hs, *p_t, *p_h, *p_deg, *p_pool, *p_cnt;
    cudaGetSymbolAddress((void**)&p_lin,  g_lin);
    cudaGetSymbolAddress((void**)&p_hs,   g_hs);
    cudaGetSymbolAddress((void**)&p_t,    g_t);
    cudaGetSymbolAddress((void**)&p_h,    g_h);
    cudaGetSymbolAddress((void**)&p_deg,  g_deg);
    cudaGetSymbolAddress((void**)&p_pool, g_pool);
    cudaGetSymbolAddress((void**)&p_cnt,  g_cnt);

    const int NH = N * H;
    const int gemm_grid = (N + 127) / 128;
    const int scat_grid = (E * 32 + 255) / 256;

    // degrees + normalization
    zero_kernel<<<(N + 255) / 256, 256>>>(p_deg, N);
    deg_kernel<<<(E + 255) / 256, 256>>>(dst);
    dinv_kernel<<<(N + 255) / 256, 256>>>();

    // ---- layer 1 ----
    gemm_kernel<IN><<<gemm_grid, 256>>>(x, W1, p_lin, p_hs);
    zero_kernel<<<(NH + 255) / 256, 256>>>(p_t, NH);
    scatter_kernel<<<scat_grid, 256>>>(src, dst, p_hs, p_t);
    epilogue_kernel<<<(NH / 4 + 255) / 256, 256>>>(p_lin, p_t, b1, p_h);

    // ---- layer 2 ----
    gemm_kernel<H><<<gemm_grid, 256>>>(p_h, W2, p_lin, p_hs);
    zero_kernel<<<(NH + 255) / 256, 256>>>(p_t, NH);
    scatter_kernel<<<scat_grid, 256>>>(src, dst, p_hs, p_t);
    epilogue_kernel<<<(NH / 4 + 255) / 256, 256>>>(p_lin, p_t, b2, p_h);

    // ---- pool + head ----
    zero_kernel<<<(G * H + 255) / 256, 256>>>(p_pool, G * H);
    zero_kernel<<<1, G>>>(p_cnt, G);
    pool_kernel<<<200, 256>>>(bat, p_h);
    head_kernel<<<1, G * C * 32>>>(Wlin, blin, out);
}

// round 3
// speedup vs baseline: 1.0705x; 1.0705x over previous
#include <cuda_runtime.h>
#include <cuda_bf16.h>

namespace {

constexpr int N  = 50000;
constexpr int E  = 1600000;
constexpr int IN = 512;
constexpr int H  = 128;
constexpr int C  = 2;
constexpr int G  = 8;

__device__ float g_lin[(size_t)N * H];
__device__ float g_hs [(size_t)N * H];
__device__ float g_t  [(size_t)N * H];
__device__ float g_h  [(size_t)N * H];
__device__ float g_dinv[N];
__device__ float g_deg [N];
__device__ float g_pool[G * H];
__device__ float g_cnt [G];

__global__ void zero_kernel(float* __restrict__ p, int n) {
    int i = blockIdx.x * blockDim.x + threadIdx.x;
    if (i < n) p[i] = 0.0f;
}

__global__ void deg_kernel(const int* __restrict__ dst) {
    int e = blockIdx.x * blockDim.x + threadIdx.x;
    if (e < E) atomicAdd(&g_deg[dst[e]], 1.0f);
}

__global__ void dinv_kernel() {
    int i = blockIdx.x * blockDim.x + threadIdx.x;
    if (i < N) g_dinv[i] = rsqrtf(g_deg[i] + 1.0f);
}

__device__ __forceinline__ unsigned f2tf32(float f) {
    unsigned r;
    asm("cvt.rna.tf32.f32 %0, %1;" : "=r"(r) : "f"(f));
    return r;
}

__device__ __forceinline__ void mma_tf32(float* d, const unsigned* a, const unsigned* b) {
    asm volatile("mma.sync.aligned.m16n8k8.row.col.f32.tf32.tf32.f32 "
        "{%0,%1,%2,%3}, {%4,%5,%6,%7}, {%8,%9}, {%0,%1,%2,%3};"
        : "+f"(d[0]), "+f"(d[1]), "+f"(d[2]), "+f"(d[3])
        : "r"(a[0]), "r"(a[1]), "r"(a[2]), "r"(a[3]), "r"(b[0]), "r"(b[1]));
}

// TF32 tensor-core GEMM: lin = A[N,K] @ W[K,128]; hs = lin * dinv[row].
// Block tile 128x128, BK=16, 8 warps, warp tile 64x32 (4x4 m16n8k8).
// SMEM holds fragments in register-layout order: A-frag = 1x LDS.128, B-frag = 1x LDS.64.
template <int K>
__global__ void __launch_bounds__(256, 2)
gemm_tf32(const float* __restrict__ A, const float* __restrict__ W,
          float* __restrict__ lin, float* __restrict__ hs) {
    constexpr int BK = 16;
    constexpr int STAGES = K / BK;

    __shared__ unsigned As[2][2][8][128];   // [buf][ks][mt][lane*4+reg]
    __shared__ unsigned Bs[2][2][16][64];   // [buf][ks][nt][lane*2+reg]

    const int tid  = threadIdx.x;
    const int lane = tid & 31;
    const int wid  = tid >> 5;
    const int wm   = wid & 1;       // 2 warp rows (64 each)
    const int wn   = wid >> 1;      // 4 warp cols (32 each)
    const int bm   = blockIdx.x * 128;

    const int a_row = tid >> 2;            // 0..63
    const int a_col = (tid & 3) * 4;       // 0,4,8,12
    const int b_row = tid >> 5;            // 0..7
    const int b_col = (tid & 31) * 4;      // 0..124

    float4 a_stage[2], b_stage[2];

    auto load_g = [&](int s) {
        const int k0 = s * BK;
        #pragma unroll
        for (int h = 0; h < 2; h++) {
            int m = bm + a_row + h * 64;
            if (m < N)
                a_stage[h] = *reinterpret_cast<const float4*>(A + (size_t)m * K + k0 + a_col);
            else
                a_stage[h] = make_float4(0.f, 0.f, 0.f, 0.f);
        }
        #pragma unroll
        for (int h = 0; h < 2; h++) {
            int kk = k0 + b_row + h * 8;
            b_stage[h] = *reinterpret_cast<const float4*>(W + (size_t)kk * H + b_col);
        }
    };

    auto store_s = [&](int buf) {
        #pragma unroll
        for (int h = 0; h < 2; h++) {
            int m  = a_row + h * 64;
            int mt = m >> 4, r = m & 15;
            const float* v = &a_stage[h].x;
            #pragma unroll
            for (int c = 0; c < 4; c++) {
                int kk = a_col + c;
                int ks = kk >> 3, kc = kk & 7;
                int idx = (r & 7) * 16 + (kc & 3) * 4 + (r >> 3) + 2 * (kc >> 2);
                As[buf][ks][mt][idx] = f2tf32(v[c]);
            }
        }
        #pragma unroll
        for (int h = 0; h < 2; h++) {
            int kk = b_row + h * 8;
            int ks = kk >> 3, kc = kk & 7;
            const float* v = &b_stage[h].x;
            #pragma unroll
            for (int c = 0; c < 4; c++) {
                int n  = b_col + c;
                int nt = n >> 3, nn = n & 7;
                int idx = nn * 8 + (kc & 3) * 2 + (kc >> 2);
                Bs[buf][ks][nt][idx] = f2tf32(v[c]);
            }
        }
    };

    float acc[4][4][4];
    #pragma unroll
    for (int i = 0; i < 4; i++)
        #pragma unroll
        for (int j = 0; j < 4; j++)
            #pragma unroll
            for (int r = 0; r < 4; r++) acc[i][j][r] = 0.f;

    auto compute = [&](int buf) {
        #pragma unroll
        for (int ks = 0; ks < 2; ks++) {
            unsigned af[4][4], bf[4][2];
            #pragma unroll
            for (int mt = 0; mt < 4; mt++) {
                uint4 t = *reinterpret_cast<const uint4*>(&As[buf][ks][wm * 4 + mt][lane * 4]);
                af[mt][0] = t.x; af[mt][1] = t.y; af[mt][2] = t.z; af[mt][3] = t.w;
            }
            #pragma unroll
            for (int nt = 0; nt < 4; nt++) {
                uint2 t = *reinterpret_cast<const uint2*>(&Bs[buf][ks][wn * 4 + nt][lane * 2]);
                bf[nt][0] = t.x; bf[nt][1] = t.y;
            }
            #pragma unroll
            for (int mt = 0; mt < 4; mt++)
                #pragma unroll
                for (int nt = 0; nt < 4; nt++)
                    mma_tf32(acc[mt][nt], af[mt], bf[nt]);
        }
    };

    load_g(0);
    store_s(0);
    __syncthreads();

    for (int s = 0; s < STAGES; s++) {
        if (s + 1 < STAGES) load_g(s + 1);
        compute(s & 1);
        __syncthreads();
        if (s + 1 < STAGES) {
            store_s((s + 1) & 1);
            __syncthreads();
        }
    }

    #pragma unroll
    for (int mt = 0; mt < 4; mt++) {
        int r0 = bm + wm * 64 + mt * 16 + (lane >> 2);
        #pragma unroll
        for (int half = 0; half < 2; half++) {
            int r = r0 + half * 8;
            if (r < N) {
                float di = g_dinv[r];
                #pragma unroll
                for (int nt = 0; nt < 4; nt++) {
                    int c = wn * 32 + nt * 8 + (lane & 3) * 2;
                    float2 v = make_float2(acc[mt][nt][half * 2], acc[mt][nt][half * 2 + 1]);
                    *reinterpret_cast<float2*>(lin + (size_t)r * H + c) = v;
                    *reinterpret_cast<float2*>(hs  + (size_t)r * H + c) = make_float2(v.x * di, v.y * di);
                }
            }
        }
    }
}

// One warp per edge: lane reads float4 of hs[src] row, red.v4 into t[dst] row.
__global__ void __launch_bounds__(256)
scatter_kernel(const int* __restrict__ src, const int* __restrict__ dst,
               const float* __restrict__ hs, float* __restrict__ t) {
    int w = (blockIdx.x * 256 + threadIdx.x) >> 5;
    if (w >= E) return;
    int lane = threadIdx.x & 31;
    int s = __ldg(src + w);
    int d = __ldg(dst + w);
    float4 v = *reinterpret_cast<const float4*>(hs + (size_t)s * H + lane * 4);
    float* p = t + (size_t)d * H + lane * 4;
    asm volatile("red.global.add.v4.f32 [%0], {%1,%2,%3,%4};"
                 :: "l"(p), "f"(v.x), "f"(v.y), "f"(v.z), "f"(v.w) : "memory");
}

// h = relu(dinv*t + lin*dinv^2 + b)
__global__ void epilogue_kernel(const float* __restrict__ lin, const float* __restrict__ t,
                                const float* __restrict__ b, float* __restrict__ hout) {
    int i = blockIdx.x * blockDim.x + threadIdx.x;
    if (i >= N * H / 4) return;
    int row = i >> 5;
    int col4 = (i & 31) * 4;
    float di = g_dinv[row];
    float di2 = di * di;
    float4 tv = reinterpret_cast<const float4*>(t)[i];
    float4 lv = reinterpret_cast<const float4*>(lin)[i];
    float4 r;
    r.x = fmaxf(fmaf(di, tv.x, lv.x * di2) + b[col4 + 0], 0.f);
    r.y = fmaxf(fmaf(di, tv.y, lv.y * di2) + b[col4 + 1], 0.f);
    r.z = fmaxf(fmaf(di, tv.z, lv.z * di2) + b[col4 + 2], 0.f);
    r.w = fmaxf(fmaf(di, tv.w, lv.w * di2) + b[col4 + 3], 0.f);
    reinterpret_cast<float4*>(hout)[i] = r;
}

__global__ void __launch_bounds__(256)
pool_kernel(const int* __restrict__ batch, const float* __restrict__ h) {
    __shared__ float acc[G * H];
    __shared__ float cnt[G];
    int tid = threadIdx.x;
    for (int i = tid; i < G * H; i += 256) acc[i] = 0.f;
    if (tid < G) cnt[tid] = 0.f;
    __syncthreads();

    int nodes_per_block = (N + gridDim.x - 1) / gridDim.x;
    int n0 = blockIdx.x * nodes_per_block;
    int n1 = min(n0 + nodes_per_block, N);
    int warp = tid >> 5, lane = tid & 31;

    for (int n = n0 + warp; n < n1; n += 8) {
        int g = batch[n];
        #pragma unroll
        for (int j = 0; j < 4; j++) {
            float v = h[(size_t)n * H + lane + j * 32];
            atomicAdd(&acc[g * H + lane + j * 32], v);
        }
        if (lane == 0) atomicAdd(&cnt[g], 1.0f);
    }
    __syncthreads();

    for (int i = tid; i < G * H; i += 256)
        if (acc[i] != 0.f) atomicAdd(&g_pool[i], acc[i]);
    if (tid < G && cnt[tid] != 0.f) atomicAdd(&g_cnt[tid], cnt[tid]);
}

__global__ void head_kernel(const float* __restrict__ Wlin, const float* __restrict__ blin,
                            float* __restrict__ out) {
    int warp = threadIdx.x >> 5, lane = threadIdx.x & 31;
    if (warp >= G * C) return;
    int g = warp >> 1, c = warp & 1;
    float s = 0.f;
    for (int d = lane; d < H; d += 32)
        s += g_pool[g * H + d] * Wlin[d * C + c];
    #pragma unroll
    for (int o = 16; o; o >>= 1) s += __shfl_xor_sync(0xffffffff, s, o);
    if (lane == 0) out[g * C + c] = s / fmaxf(g_cnt[g], 1.0f) + blin[c];
}

} // namespace

extern "C" void kernel_launch(void* const* d_in, const int* in_sizes, int n_in,
                              void* d_out, int out_size) {
    const float* x    = (const float*)d_in[0];
    const int*   ei   = (const int*)  d_in[1];
    const int*   bat  = (const int*)  d_in[2];
    const float* W1   = (const float*)d_in[3];
    const float* b1   = (const float*)d_in[4];
    const float* W2   = (const float*)d_in[5];
    const float* b2   = (const float*)d_in[6];
    const float* Wlin = (const float*)d_in[7];
    const float* blin = (const float*)d_in[8];
    float* out = (float*)d_out;
    const int* src = ei;
    const int* dst = ei + E;

    float *p_lin, *p_hs, *p_t, *p_h, *p_deg, *p_pool, *p_cnt;
    cudaGetSymbolAddress((void**)&p_lin,  g_lin);
    cudaGetSymbolAddress((void**)&p_hs,   g_hs);
    cudaGetSymbolAddress((void**)&p_t,    g_t);
    cudaGetSymbolAddress((void**)&p_h,    g_h);
    cudaGetSymbolAddress((void**)&p_deg,  g_deg);
    cudaGetSymbolAddress((void**)&p_pool, g_pool);
    cudaGetSymbolAddress((void**)&p_cnt,  g_cnt);

    const int NH = N * H;
    const int gemm_grid = (N + 127) / 128;
    const int scat_grid = (E * 32 + 255) / 256;

    // degrees + normalization
    zero_kernel<<<(N + 255) / 256, 256>>>(p_deg, N);
    deg_kernel<<<(E + 255) / 256, 256>>>(dst);
    dinv_kernel<<<(N + 255) / 256, 256>>>();

    // ---- layer 1 ----
    gemm_tf32<IN><<<gemm_grid, 256>>>(x, W1, p_lin, p_hs);
    zero_kernel<<<(NH + 255) / 256, 256>>>(p_t, NH);
    scatter_kernel<<<scat_grid, 256>>>(src, dst, p_hs, p_t);
    epilogue_kernel<<<(NH / 4 + 255) / 256, 256>>>(p_lin, p_t, b1, p_h);

    // ---- layer 2 ----
    gemm_tf32<H><<<gemm_grid, 256>>>(p_h, W2, p_lin, p_hs);
    zero_kernel<<<(NH + 255) / 256, 256>>>(p_t, NH);
    scatter_kernel<<<scat_grid, 256>>>(src, dst, p_hs, p_t);
    epilogue_kernel<<<(NH / 4 + 255) / 256, 256>>>(p_lin, p_t, b2, p_h);

    // ---- pool + head ----
    zero_kernel<<<(G * H + 255) / 256, 256>>>(p_pool, G * H);
    zero_kernel<<<1, G>>>(p_cnt, G);
    pool_kernel<<<200, 256>>>(bat, p_h);
    head_kernel<<<1, G * C * 32>>>(Wlin, blin, out);
}

// round 4
// speedup vs baseline: 2.4737x; 2.3108x over previous
#include <cuda_runtime.h>
#include <cuda_bf16.h>

namespace {

constexpr int N  = 50000;
constexpr int E  = 1600000;
constexpr int IN = 512;
constexpr int H  = 128;
constexpr int C  = 2;
constexpr int G  = 8;
constexpr int NB_SCAN = (N + 255) / 256;   // 196 scan blocks

// ---- scratch (static device arrays; no runtime allocation) ----
__device__ float g_hs [(size_t)N * H];   // gemm output, pre-scaled by dinv[row]
__device__ float g_h  [(size_t)N * H];   // layer output (post aggregation+relu)
__device__ float g_dinv[N];
__device__ int   g_cnt [N];              // in-degree counts
__device__ int   g_incl[N];              // per-block inclusive scan
__device__ int   g_bsum[256];
__device__ int   g_boff[256];
__device__ int   g_rowptr[N + 1];
__device__ int   g_cursor[N];
__device__ int   g_adj[E];               // src indices grouped by dst
__device__ float g_pool[G * H];
__device__ float g_cntf[G];

// ======================= small utility kernels =======================

__global__ void zero_f(float* __restrict__ p, int n) {
    int i = blockIdx.x * blockDim.x + threadIdx.x;
    if (i < n) p[i] = 0.0f;
}
__global__ void zero_i(int* __restrict__ p, int n) {
    int i = blockIdx.x * blockDim.x + threadIdx.x;
    if (i < n) p[i] = 0;
}

__global__ void count_kernel(const int* __restrict__ dst) {
    int e = blockIdx.x * blockDim.x + threadIdx.x;
    if (e < E) atomicAdd(&g_cnt[dst[e]], 1);
}

// Per-block inclusive scan of counts
__global__ void scanA_kernel() {
    __shared__ int sm[256];
    int t = threadIdx.x;
    int i = blockIdx.x * 256 + t;
    int v = (i < N) ? g_cnt[i] : 0;
    sm[t] = v;
    __syncthreads();
    #pragma unroll
    for (int off = 1; off < 256; off <<= 1) {
        int u = (t >= off) ? sm[t - off] : 0;
        __syncthreads();
        sm[t] += u;
        __syncthreads();
    }
    if (i < N) g_incl[i] = sm[t];
    if (t == 255) g_bsum[blockIdx.x] = sm[255];
}

// Scan block sums (exclusive)
__global__ void scanB_kernel() {
    __shared__ int sm[256];
    int t = threadIdx.x;
    int v = (t < NB_SCAN) ? g_bsum[t] : 0;
    sm[t] = v;
    __syncthreads();
    #pragma unroll
    for (int off = 1; off < 256; off <<= 1) {
        int u = (t >= off) ? sm[t - off] : 0;
        __syncthreads();
        sm[t] += u;
        __syncthreads();
    }
    g_boff[t] = sm[t] - v;   // exclusive
}

__global__ void scanC_kernel() {
    int i = blockIdx.x * blockDim.x + threadIdx.x;
    if (i < N) {
        g_rowptr[i + 1] = g_incl[i] + g_boff[i >> 8];
        if (i == 0) g_rowptr[0] = 0;
    }
}

__global__ void scanD_kernel() {
    int i = blockIdx.x * blockDim.x + threadIdx.x;
    if (i < N) {
        g_cursor[i] = g_rowptr[i];
        g_dinv[i] = rsqrtf((float)g_cnt[i] + 1.0f);
    }
}

__global__ void fill_kernel(const int* __restrict__ src, const int* __restrict__ dst) {
    int e = blockIdx.x * blockDim.x + threadIdx.x;
    if (e < E) {
        int d = dst[e];
        int pos = atomicAdd(&g_cursor[d], 1);
        g_adj[pos] = src[e];
    }
}

// ======================= tf32 tensor-core GEMM =======================
// hs[r, 0:128] = (A[r, :] @ W) * dinv[r]
// Block tile 256x128, 8 warps (4 wm x 2 wn), warp tile 64x64, BK=32.
// Natural row-major SMEM with padded rows (conflict-free scalar frag loads),
// cp.async double-buffered GMEM->SMEM (no register staging, no STS).

__device__ __forceinline__ void mma_tf32(float* d, const unsigned* a, const unsigned* b) {
    asm volatile("mma.sync.aligned.m16n8k8.row.col.f32.tf32.tf32.f32 "
        "{%0,%1,%2,%3}, {%4,%5,%6,%7}, {%8,%9}, {%0,%1,%2,%3};"
        : "+f"(d[0]), "+f"(d[1]), "+f"(d[2]), "+f"(d[3])
        : "r"(a[0]), "r"(a[1]), "r"(a[2]), "r"(a[3]), "r"(b[0]), "r"(b[1]));
}

__device__ __forceinline__ void cp16(void* smem_dst, const void* gmem_src, int src_bytes) {
    unsigned sa = (unsigned)__cvta_generic_to_shared(smem_dst);
    asm volatile("cp.async.cg.shared.global [%0], [%1], 16, %2;"
                 :: "r"(sa), "l"(gmem_src), "r"(src_bytes) : "memory");
}
__device__ __forceinline__ void cp_commit() {
    asm volatile("cp.async.commit_group;" ::: "memory");
}
template <int Nw>
__device__ __forceinline__ void cp_wait() {
    asm volatile("cp.async.wait_group %0;" :: "n"(Nw) : "memory");
}

// round-to-nearest to tf32 by bit trick: HW truncates low 13 bits of operand.
__device__ __forceinline__ unsigned rtf(float f) {
    return __float_as_uint(f) + 0x1000u;
}

constexpr int APAD = 36;    // banks (4g + c) distinct
constexpr int BPAD = 136;   // banks (8k' + n') distinct
constexpr int ASZ  = 2 * 256 * APAD;
constexpr int BSZ  = 2 * 32 * BPAD;
constexpr size_t GEMM_SMEM = (size_t)(ASZ + BSZ) * 4;

template <int K>
__global__ void __launch_bounds__(256)
gemm_cp(const float* __restrict__ A, const float* __restrict__ W,
        float* __restrict__ hs) {
    constexpr int BK = 32;
    constexpr int STAGES = K / BK;

    extern __shared__ float smem[];
    float* As = smem;          // [2][256][APAD]
    float* Bs = smem + ASZ;    // [2][32][BPAD]

    const int tid  = threadIdx.x;
    const int lane = tid & 31;
    const int wid  = tid >> 5;
    const int wm   = wid >> 1;   // 0..3  (64-row group)
    const int wn   = wid & 1;    // 0..1  (64-col group)
    const int bm   = blockIdx.x * 256;

    auto AS = [&](int b, int r, int c) -> float& { return As[b * (256 * APAD) + r * APAD + c]; };
    auto BS = [&](int b, int k, int n) -> float& { return Bs[b * (32 * BPAD) + k * BPAD + n]; };

    auto issue = [&](int s, int buf) {
        const int k0 = s * BK;
        // A: 256 rows x 32 cols. thread: rows tid>>1 (+128), chunks (tid&1)+2j.
        #pragma unroll
        for (int i = 0; i < 2; i++) {
            int r = (tid >> 1) + i * 128;
            int gr = bm + r;
            int sz = (gr < N) ? 16 : 0;
            const float* srow = A + (size_t)gr * K + k0;
            #pragma unroll
            for (int j = 0; j < 4; j++) {
                int ch = (tid & 1) + 2 * j;
                cp16(&AS(buf, r, ch * 4), srow + ch * 4, sz);
            }
        }
        // B: 32 rows(k) x 128 cols. thread: k=tid>>3, chunks (tid&7)+8j.
        {
            int k = tid >> 3;
            const float* srow = W + (size_t)(k0 + k) * H;
            #pragma unroll
            for (int j = 0; j < 4; j++) {
                int ch = (tid & 7) + 8 * j;
                cp16(&BS(buf, k, ch * 4), srow + ch * 4, 16);
            }
        }
        cp_commit();
    };

    float acc[4][8][4];
    #pragma unroll
    for (int i = 0; i < 4; i++)
        #pragma unroll
        for (int j = 0; j < 8; j++)
            #pragma unroll
            for (int r = 0; r < 4; r++) acc[i][j][r] = 0.f;

    const int gid = lane >> 2;   // 0..7
    const int cid = lane & 3;    // 0..3

    auto compute = [&](int buf) {
        #pragma unroll
        for (int ks = 0; ks < 4; ks++) {
            const int c0 = ks * 8 + cid;
            unsigned af[4][4];
            #pragma unroll
            for (int mt = 0; mt < 4; mt++) {
                int r = wm * 64 + mt * 16 + gid;
                af[mt][0] = rtf(AS(buf, r,     c0));
                af[mt][1] = rtf(AS(buf, r + 8, c0));
                af[mt][2] = rtf(AS(buf, r,     c0 + 4));
                af[mt][3] = rtf(AS(buf, r + 8, c0 + 4));
            }
            unsigned bf[8][2];
            #pragma unroll
            for (int nt = 0; nt < 8; nt++) {
                int n = wn * 64 + nt * 8 + gid;
                bf[nt][0] = rtf(BS(buf, ks * 8 + cid,     n));
                bf[nt][1] = rtf(BS(buf, ks * 8 + cid + 4, n));
            }
            #pragma unroll
            for (int mt = 0; mt < 4; mt++)
                #pragma unroll
                for (int nt = 0; nt < 8; nt++)
                    mma_tf32(acc[mt][nt], af[mt], bf[nt]);
        }
    };

    issue(0, 0);
    for (int s = 0; s < STAGES; s++) {
        if (s + 1 < STAGES) {
            issue(s + 1, (s + 1) & 1);
            cp_wait<1>();
        } else {
            cp_wait<0>();
        }
        __syncthreads();
        compute(s & 1);
        __syncthreads();
    }

    // epilogue: hs = acc * dinv[row]
    #pragma unroll
    for (int mt = 0; mt < 4; mt++) {
        #pragma unroll
        for (int half = 0; half < 2; half++) {
            int r = bm + wm * 64 + mt * 16 + gid + half * 8;
            if (r < N) {
                float di = g_dinv[r];
                #pragma unroll
                for (int nt = 0; nt < 8; nt++) {
                    int c = wn * 64 + nt * 8 + cid * 2;
                    float2 v = make_float2(acc[mt][nt][half * 2] * di,
                                           acc[mt][nt][half * 2 + 1] * di);
                    *reinterpret_cast<float2*>(hs + (size_t)r * H + c) = v;
                }
            }
        }
    }
}

// ======================= CSR aggregation (atomic-free) =======================
// warp per node: h[d,:] = relu(dinv[d] * (hs[d,:] + sum_{s in adj[d]} hs[s,:]) + b)
__global__ void __launch_bounds__(256)
agg_kernel(const float* __restrict__ hs, const float* __restrict__ bias,
           float* __restrict__ h) {
    int w = (blockIdx.x * 256 + threadIdx.x) >> 5;
    if (w >= N) return;
    int lane = threadIdx.x & 31;
    const float4* hs4 = reinterpret_cast<const float4*>(hs);

    int beg = __ldg(&g_rowptr[w]);
    int end = __ldg(&g_rowptr[w + 1]);

    float4 acc = __ldg(&hs4[(size_t)w * 32 + lane]);   // self term
    int e = beg;
    for (; e + 4 <= end; e += 4) {
        int s0 = __ldg(&g_adj[e]);
        int s1 = __ldg(&g_adj[e + 1]);
        int s2 = __ldg(&g_adj[e + 2]);
        int s3 = __ldg(&g_adj[e + 3]);
        float4 v0 = __ldg(&hs4[(size_t)s0 * 32 + lane]);
        float4 v1 = __ldg(&hs4[(size_t)s1 * 32 + lane]);
        float4 v2 = __ldg(&hs4[(size_t)s2 * 32 + lane]);
        float4 v3 = __ldg(&hs4[(size_t)s3 * 32 + lane]);
        acc.x += (v0.x + v1.x) + (v2.x + v3.x);
        acc.y += (v0.y + v1.y) + (v2.y + v3.y);
        acc.z += (v0.z + v1.z) + (v2.z + v3.z);
        acc.w += (v0.w + v1.w) + (v2.w + v3.w);
    }
    for (; e < end; e++) {
        int s0 = __ldg(&g_adj[e]);
        float4 v0 = __ldg(&hs4[(size_t)s0 * 32 + lane]);
        acc.x += v0.x; acc.y += v0.y; acc.z += v0.z; acc.w += v0.w;
    }
    float di = g_dinv[w];
    float4 bb = __ldg(&reinterpret_cast<const float4*>(bias)[lane]);
    float4 r;
    r.x = fmaxf(fmaf(di, acc.x, bb.x), 0.f);
    r.y = fmaxf(fmaf(di, acc.y, bb.y), 0.f);
    r.z = fmaxf(fmaf(di, acc.z, bb.z), 0.f);
    r.w = fmaxf(fmaf(di, acc.w, bb.w), 0.f);
    reinterpret_cast<float4*>(h)[(size_t)w * 32 + lane] = r;
}

// ======================= pooling + head =======================

__global__ void __launch_bounds__(256)
pool_kernel(const int* __restrict__ batch, const float* __restrict__ h) {
    __shared__ float acc[G * H];
    __shared__ float cnt[G];
    int tid = threadIdx.x;
    for (int i = tid; i < G * H; i += 256) acc[i] = 0.f;
    if (tid < G) cnt[tid] = 0.f;
    __syncthreads();

    int nodes_per_block = (N + gridDim.x - 1) / gridDim.x;
    int n0 = blockIdx.x * nodes_per_block;
    int n1 = min(n0 + nodes_per_block, N);
    int warp = tid >> 5, lane = tid & 31;

    for (int n = n0 + warp; n < n1; n += 8) {
        int g = batch[n];
        #pragma unroll
        for (int j = 0; j < 4; j++) {
            float v = h[(size_t)n * H + lane + j * 32];
            atomicAdd(&acc[g * H + lane + j * 32], v);
        }
        if (lane == 0) atomicAdd(&cnt[g], 1.0f);
    }
    __syncthreads();

    for (int i = tid; i < G * H; i += 256)
        if (acc[i] != 0.f) atomicAdd(&g_pool[i], acc[i]);
    if (tid < G && cnt[tid] != 0.f) atomicAdd(&g_cntf[tid], cnt[tid]);
}

__global__ void head_kernel(const float* __restrict__ Wlin, const float* __restrict__ blin,
                            float* __restrict__ out) {
    int warp = threadIdx.x >> 5, lane = threadIdx.x & 31;
    if (warp >= G * C) return;
    int g = warp >> 1, c = warp & 1;
    float s = 0.f;
    for (int d = lane; d < H; d += 32)
        s += g_pool[g * H + d] * Wlin[d * C + c];
    #pragma unroll
    for (int o = 16; o; o >>= 1) s += __shfl_xor_sync(0xffffffff, s, o);
    if (lane == 0) out[g * C + c] = s / fmaxf(g_cntf[g], 1.0f) + blin[c];
}

} // namespace

extern "C" void kernel_launch(void* const* d_in, const int* in_sizes, int n_in,
                              void* d_out, int out_size) {
    const float* x    = (const float*)d_in[0];
    const int*   ei   = (const int*)  d_in[1];
    const int*   bat  = (const int*)  d_in[2];
    const float* W1   = (const float*)d_in[3];
    const float* b1   = (const float*)d_in[4];
    const float* W2   = (const float*)d_in[5];
    const float* b2   = (const float*)d_in[6];
    const float* Wlin = (const float*)d_in[7];
    const float* blin = (const float*)d_in[8];
    float* out = (float*)d_out;
    const int* src = ei;
    const int* dst = ei + E;

    float *p_hs, *p_h, *p_pool, *p_cntf;
    int* p_cnt;
    cudaGetSymbolAddress((void**)&p_hs,   g_hs);
    cudaGetSymbolAddress((void**)&p_h,    g_h);
    cudaGetSymbolAddress((void**)&p_pool, g_pool);
    cudaGetSymbolAddress((void**)&p_cntf, g_cntf);
    cudaGetSymbolAddress((void**)&p_cnt,  g_cnt);

    cudaFuncSetAttribute(gemm_cp<IN>, cudaFuncAttributeMaxDynamicSharedMemorySize, (int)GEMM_SMEM);
    cudaFuncSetAttribute(gemm_cp<H>,  cudaFuncAttributeMaxDynamicSharedMemorySize, (int)GEMM_SMEM);

    const int gemm_grid = (N + 255) / 256;       // 196
    const int agg_grid  = (N * 32 + 255) / 256;  // warp per node
    const int nthr_grid = (N + 255) / 256;
    const int e_grid    = (E + 255) / 256;

    // ---- CSR build + normalization ----
    zero_i<<<nthr_grid, 256>>>(p_cnt, N);
    count_kernel<<<e_grid, 256>>>(dst);
    scanA_kernel<<<NB_SCAN, 256>>>();
    scanB_kernel<<<1, 256>>>();
    scanC_kernel<<<nthr_grid, 256>>>();
    scanD_kernel<<<nthr_grid, 256>>>();
    fill_kernel<<<e_grid, 256>>>(src, dst);

    // ---- layer 1 ----
    gemm_cp<IN><<<gemm_grid, 256, GEMM_SMEM>>>(x, W1, p_hs);
    agg_kernel<<<agg_grid, 256>>>(p_hs, b1, p_h);

    // ---- layer 2 ----
    gemm_cp<H><<<gemm_grid, 256, GEMM_SMEM>>>(p_h, W2, p_hs);
    agg_kernel<<<agg_grid, 256>>>(p_hs, b2, p_h);

    // ---- pool + head ----
    zero_f<<<(G * H + 255) / 256, 256>>>(p_pool, G * H);
    zero_f<<<1, G>>>(p_cntf, G);
    pool_kernel<<<200, 256>>>(bat, p_h);
    head_kernel<<<1, G * C * 32>>>(Wlin, blin, out);
}

// round 5
// speedup vs baseline: 2.6667x; 1.0780x over previous
#include <cuda_runtime.h>
#include <cuda_fp16.h>

namespace {

constexpr int N  = 50000;
constexpr int E  = 1600000;
constexpr int IN = 512;
constexpr int H  = 128;
constexpr int C  = 2;
constexpr int G  = 8;
constexpr int NB_SCAN = (N + 255) / 256;   // 196 scan blocks

// ---- scratch (static device arrays; zero-initialized at load) ----
__device__ __half g_hs [(size_t)N * H];  // gemm output * dinv[row], fp16
__device__ float  g_h  [(size_t)N * H];  // layer output (post aggregation+relu)
__device__ float  g_dinv[N];
__device__ int    g_cnt [N];             // in-degree counts (zeroed at END of each call)
__device__ int    g_incl[N];
__device__ int    g_bsum[256];
__device__ int    g_boff[256];
__device__ int    g_rowptr[N + 1];
__device__ int    g_cursor[N];
__device__ int    g_adj[E];              // src indices grouped by dst
__device__ float  g_pool[G * H];
__device__ float  g_cntf[G];

// ======================= CSR build =======================

__global__ void count_kernel(const int* __restrict__ dst) {
    int e = blockIdx.x * blockDim.x + threadIdx.x;
    if (e < E) atomicAdd(&g_cnt[dst[e]], 1);
}

__global__ void scanA_kernel() {
    __shared__ int sm[256];
    int t = threadIdx.x;
    int i = blockIdx.x * 256 + t;
    int v = (i < N) ? g_cnt[i] : 0;
    sm[t] = v;
    __syncthreads();
    #pragma unroll
    for (int off = 1; off < 256; off <<= 1) {
        int u = (t >= off) ? sm[t - off] : 0;
        __syncthreads();
        sm[t] += u;
        __syncthreads();
    }
    if (i < N) g_incl[i] = sm[t];
    if (t == 255) g_bsum[blockIdx.x] = sm[255];
}

__global__ void scanB_kernel() {
    __shared__ int sm[256];
    int t = threadIdx.x;
    int v = (t < NB_SCAN) ? g_bsum[t] : 0;
    sm[t] = v;
    __syncthreads();
    #pragma unroll
    for (int off = 1; off < 256; off <<= 1) {
        int u = (t >= off) ? sm[t - off] : 0;
        __syncthreads();
        sm[t] += u;
        __syncthreads();
    }
    g_boff[t] = sm[t] - v;   // exclusive
}

// rowptr[i+1], cursor[i] = rowptr[i], dinv[i] in one pass
__global__ void scanCD_kernel() {
    int i = blockIdx.x * blockDim.x + threadIdx.x;
    if (i < N) {
        int c = g_cnt[i];
        int inc = g_incl[i] + g_boff[i >> 8];
        g_rowptr[i + 1] = inc;
        g_cursor[i] = inc - c;
        g_dinv[i] = rsqrtf((float)c + 1.0f);
        if (i == 0) g_rowptr[0] = 0;
    }
}

__global__ void fill_kernel(const int* __restrict__ src, const int* __restrict__ dst) {
    int e = blockIdx.x * blockDim.x + threadIdx.x;
    if (e < E) {
        int d = dst[e];
        int pos = atomicAdd(&g_cursor[d], 1);
        g_adj[pos] = src[e];
    }
}

__global__ void zero_cnt_kernel() {     // runs LAST: leaves g_cnt zeroed for next call
    int i = blockIdx.x * blockDim.x + threadIdx.x;
    if (i < N) g_cnt[i] = 0;
}

// ======================= tf32 tensor-core GEMM =======================
// hs[r, 0:128] = half( (A[r,:] @ W) * dinv[r] )
// Block tile 256x128, 8 warps (4 wm x 2 wn), warp tile 64x64, BK=32,
// cp.async double-buffered, padded row-major SMEM (conflict-free frag loads).

__device__ __forceinline__ void mma_tf32(float* d, const unsigned* a, const unsigned* b) {
    asm volatile("mma.sync.aligned.m16n8k8.row.col.f32.tf32.tf32.f32 "
        "{%0,%1,%2,%3}, {%4,%5,%6,%7}, {%8,%9}, {%0,%1,%2,%3};"
        : "+f"(d[0]), "+f"(d[1]), "+f"(d[2]), "+f"(d[3])
        : "r"(a[0]), "r"(a[1]), "r"(a[2]), "r"(a[3]), "r"(b[0]), "r"(b[1]));
}

__device__ __forceinline__ void cp16(void* smem_dst, const void* gmem_src, int src_bytes) {
    unsigned sa = (unsigned)__cvta_generic_to_shared(smem_dst);
    asm volatile("cp.async.cg.shared.global [%0], [%1], 16, %2;"
                 :: "r"(sa), "l"(gmem_src), "r"(src_bytes) : "memory");
}
__device__ __forceinline__ void cp_commit() {
    asm volatile("cp.async.commit_group;" ::: "memory");
}
template <int Nw>
__device__ __forceinline__ void cp_wait() {
    asm volatile("cp.async.wait_group %0;" :: "n"(Nw) : "memory");
}

// round-to-nearest tf32 via bit trick (HW truncates low 13 bits of operand)
__device__ __forceinline__ unsigned rtf(float f) {
    return __float_as_uint(f) + 0x1000u;
}

constexpr int APAD = 36;
constexpr int BPAD = 136;
constexpr int ASZ  = 2 * 256 * APAD;
constexpr int BSZ  = 2 * 32 * BPAD;
constexpr size_t GEMM_SMEM = (size_t)(ASZ + BSZ) * 4;

template <int K>
__global__ void __launch_bounds__(256)
gemm_cp(const float* __restrict__ A, const float* __restrict__ W,
        __half* __restrict__ hs) {
    constexpr int BK = 32;
    constexpr int STAGES = K / BK;

    extern __shared__ float smem[];
    float* As = smem;          // [2][256][APAD]
    float* Bs = smem + ASZ;    // [2][32][BPAD]

    const int tid  = threadIdx.x;
    const int lane = tid & 31;
    const int wid  = tid >> 5;
    const int wm   = wid >> 1;
    const int wn   = wid & 1;
    const int bm   = blockIdx.x * 256;

    auto AS = [&](int b, int r, int c) -> float& { return As[b * (256 * APAD) + r * APAD + c]; };
    auto BS = [&](int b, int k, int n) -> float& { return Bs[b * (32 * BPAD) + k * BPAD + n]; };

    auto issue = [&](int s, int buf) {
        const int k0 = s * BK;
        #pragma unroll
        for (int i = 0; i < 2; i++) {
            int r = (tid >> 1) + i * 128;
            int gr = bm + r;
            int sz = (gr < N) ? 16 : 0;
            const float* srow = A + (size_t)gr * K + k0;
            #pragma unroll
            for (int j = 0; j < 4; j++) {
                int ch = (tid & 1) + 2 * j;
                cp16(&AS(buf, r, ch * 4), srow + ch * 4, sz);
            }
        }
        {
            int k = tid >> 3;
            const float* srow = W + (size_t)(k0 + k) * H;
            #pragma unroll
            for (int j = 0; j < 4; j++) {
                int ch = (tid & 7) + 8 * j;
                cp16(&BS(buf, k, ch * 4), srow + ch * 4, 16);
            }
        }
        cp_commit();
    };

    float acc[4][8][4];
    #pragma unroll
    for (int i = 0; i < 4; i++)
        #pragma unroll
        for (int j = 0; j < 8; j++)
            #pragma unroll
            for (int r = 0; r < 4; r++) acc[i][j][r] = 0.f;

    const int gid = lane >> 2;
    const int cid = lane & 3;

    auto compute = [&](int buf) {
        #pragma unroll
        for (int ks = 0; ks < 4; ks++) {
            const int c0 = ks * 8 + cid;
            unsigned af[4][4];
            #pragma unroll
            for (int mt = 0; mt < 4; mt++) {
                int r = wm * 64 + mt * 16 + gid;
                af[mt][0] = rtf(AS(buf, r,     c0));
                af[mt][1] = rtf(AS(buf, r + 8, c0));
                af[mt][2] = rtf(AS(buf, r,     c0 + 4));
                af[mt][3] = rtf(AS(buf, r + 8, c0 + 4));
            }
            unsigned bf[8][2];
            #pragma unroll
            for (int nt = 0; nt < 8; nt++) {
                int n = wn * 64 + nt * 8 + gid;
                bf[nt][0] = rtf(BS(buf, ks * 8 + cid,     n));
                bf[nt][1] = rtf(BS(buf, ks * 8 + cid + 4, n));
            }
            #pragma unroll
            for (int mt = 0; mt < 4; mt++)
                #pragma unroll
                for (int nt = 0; nt < 8; nt++)
                    mma_tf32(acc[mt][nt], af[mt], bf[nt]);
        }
    };

    issue(0, 0);
    for (int s = 0; s < STAGES; s++) {
        if (s + 1 < STAGES) {
            issue(s + 1, (s + 1) & 1);
            cp_wait<1>();
        } else {
            cp_wait<0>();
        }
        __syncthreads();
        compute(s & 1);
        __syncthreads();
    }

    #pragma unroll
    for (int mt = 0; mt < 4; mt++) {
        #pragma unroll
        for (int half = 0; half < 2; half++) {
            int r = bm + wm * 64 + mt * 16 + gid + half * 8;
            if (r < N) {
                float di = g_dinv[r];
                #pragma unroll
                for (int nt = 0; nt < 8; nt++) {
                    int c = wn * 64 + nt * 8 + cid * 2;
                    __half2 v = __floats2half2_rn(acc[mt][nt][half * 2] * di,
                                                  acc[mt][nt][half * 2 + 1] * di);
                    *reinterpret_cast<__half2*>(hs + (size_t)r * H + c) = v;
                }
            }
        }
    }
}

// ======================= CSR aggregation (fp16 gather, fp32 accum) =======================
// warp per node: h[d,:] = relu(dinv[d] * (hs[d,:] + sum_{s in adj[d]} hs[s,:]) + b)
__device__ __forceinline__ void acc_row(float4& acc, uint2 u) {
    float2 f0 = __half22float2(*reinterpret_cast<__half2*>(&u.x));
    float2 f1 = __half22float2(*reinterpret_cast<__half2*>(&u.y));
    acc.x += f0.x; acc.y += f0.y; acc.z += f1.x; acc.w += f1.y;
}

__global__ void __launch_bounds__(256)
agg_kernel(const __half* __restrict__ hs, const float* __restrict__ bias,
           float* __restrict__ h) {
    int w = (blockIdx.x * 256 + threadIdx.x) >> 5;
    if (w >= N) return;
    int lane = threadIdx.x & 31;
    const uint2* hs2 = reinterpret_cast<const uint2*>(hs);   // 4 halfs per lane

    int beg = __ldg(&g_rowptr[w]);
    int end = __ldg(&g_rowptr[w + 1]);

    float4 acc = make_float4(0.f, 0.f, 0.f, 0.f);
    acc_row(acc, __ldg(&hs2[(size_t)w * 32 + lane]));        // self term

    int e = beg;
    for (; e + 4 <= end; e += 4) {
        int s0 = __ldg(&g_adj[e]);
        int s1 = __ldg(&g_adj[e + 1]);
        int s2 = __ldg(&g_adj[e + 2]);
        int s3 = __ldg(&g_adj[e + 3]);
        uint2 v0 = __ldg(&hs2[(size_t)s0 * 32 + lane]);
        uint2 v1 = __ldg(&hs2[(size_t)s1 * 32 + lane]);
        uint2 v2 = __ldg(&hs2[(size_t)s2 * 32 + lane]);
        uint2 v3 = __ldg(&hs2[(size_t)s3 * 32 + lane]);
        acc_row(acc, v0); acc_row(acc, v1);
        acc_row(acc, v2); acc_row(acc, v3);
    }
    for (; e < end; e++) {
        int s0 = __ldg(&g_adj[e]);
        acc_row(acc, __ldg(&hs2[(size_t)s0 * 32 + lane]));
    }

    float di = g_dinv[w];
    float4 bb = __ldg(&reinterpret_cast<const float4*>(bias)[lane]);
    float4 r;
    r.x = fmaxf(fmaf(di, acc.x, bb.x), 0.f);
    r.y = fmaxf(fmaf(di, acc.y, bb.y), 0.f);
    r.z = fmaxf(fmaf(di, acc.z, bb.z), 0.f);
    r.w = fmaxf(fmaf(di, acc.w, bb.w), 0.f);
    reinterpret_cast<float4*>(h)[(size_t)w * 32 + lane] = r;
}

// ======================= pooling + head =======================

__global__ void zero_pool_kernel() {
    int i = blockIdx.x * blockDim.x + threadIdx.x;
    if (i < G * H) g_pool[i] = 0.f;
    if (i < G) g_cntf[i] = 0.f;
}

__global__ void __launch_bounds__(256)
pool_kernel(const int* __restrict__ batch, const float* __restrict__ h) {
    __shared__ float acc[G * H];
    __shared__ float cnt[G];
    int tid = threadIdx.x;
    for (int i = tid; i < G * H; i += 256) acc[i] = 0.f;
    if (tid < G) cnt[tid] = 0.f;
    __syncthreads();

    int nodes_per_block = (N + gridDim.x - 1) / gridDim.x;
    int n0 = blockIdx.x * nodes_per_block;
    int n1 = min(n0 + nodes_per_block, N);
    int warp = tid >> 5, lane = tid & 31;

    for (int n = n0 + warp; n < n1; n += 8) {
        int g = batch[n];
        #pragma unroll
        for (int j = 0; j < 4; j++) {
            float v = h[(size_t)n * H + lane + j * 32];
            atomicAdd(&acc[g * H + lane + j * 32], v);
        }
        if (lane == 0) atomicAdd(&cnt[g], 1.0f);
    }
    __syncthreads();

    for (int i = tid; i < G * H; i += 256)
        if (acc[i] != 0.f) atomicAdd(&g_pool[i], acc[i]);
    if (tid < G && cnt[tid] != 0.f) atomicAdd(&g_cntf[tid], cnt[tid]);
}

__global__ void head_kernel(const float* __restrict__ Wlin, const float* __restrict__ blin,
                            float* __restrict__ out) {
    int warp = threadIdx.x >> 5, lane = threadIdx.x & 31;
    if (warp >= G * C) return;
    int g = warp >> 1, c = warp & 1;
    float s = 0.f;
    for (int d = lane; d < H; d += 32)
        s += g_pool[g * H + d] * Wlin[d * C + c];
    #pragma unroll
    for (int o = 16; o; o >>= 1) s += __shfl_xor_sync(0xffffffff, s, o);
    if (lane == 0) out[g * C + c] = s / fmaxf(g_cntf[g], 1.0f) + blin[c];
}

} // namespace

extern "C" void kernel_launch(void* const* d_in, const int* in_sizes, int n_in,
                              void* d_out, int out_size) {
    const float* x    = (const float*)d_in[0];
    const int*   ei   = (const int*)  d_in[1];
    const int*   bat  = (const int*)  d_in[2];
    const float* W1   = (const float*)d_in[3];
    const float* b1   = (const float*)d_in[4];
    const float* W2   = (const float*)d_in[5];
    const float* b2   = (const float*)d_in[6];
    const float* Wlin = (const float*)d_in[7];
    const float* blin = (const float*)d_in[8];
    float* out = (float*)d_out;
    const int* src = ei;
    const int* dst = ei + E;

    __half* p_hs;
    float *p_h;
    cudaGetSymbolAddress((void**)&p_hs, g_hs);
    cudaGetSymbolAddress((void**)&p_h,  g_h);

    cudaFuncSetAttribute(gemm_cp<IN>, cudaFuncAttributeMaxDynamicSharedMemorySize, (int)GEMM_SMEM);
    cudaFuncSetAttribute(gemm_cp<H>,  cudaFuncAttributeMaxDynamicSharedMemorySize, (int)GEMM_SMEM);

    const int gemm_grid = (N + 255) / 256;
    const int agg_grid  = (N * 32 + 255) / 256;
    const int nthr_grid = (N + 255) / 256;
    const int e_grid    = (E + 255) / 256;

    // ---- CSR build (g_cnt arrives zeroed: loader on first call, tail kernel after) ----
    count_kernel<<<e_grid, 256>>>(dst);          // launch 0
    scanA_kernel<<<NB_SCAN, 256>>>();            // launch 1
    scanB_kernel<<<1, 256>>>();                  // launch 2
    scanCD_kernel<<<nthr_grid, 256>>>();         // launch 3
    fill_kernel<<<e_grid, 256>>>(src, dst);      // launch 4

    // ---- layer 1 ----
    gemm_cp<IN><<<gemm_grid, 256, GEMM_SMEM>>>(x, W1, p_hs);   // launch 5 (ncu capture)
    agg_kernel<<<agg_grid, 256>>>(p_hs, b1, p_h);

    // ---- layer 2 ----
    gemm_cp<H><<<gemm_grid, 256, GEMM_SMEM>>>(p_h, W2, p_hs);
    agg_kernel<<<agg_grid, 256>>>(p_hs, b2, p_h);

    // ---- pool + head ----
    zero_pool_kernel<<<(G * H + 255) / 256, 256>>>();
    pool_kernel<<<200, 256>>>(bat, p_h);
    head_kernel<<<1, G * C * 32>>>(Wlin, blin, out);

    // ---- reset counts for next call (keeps every call identical) ----
    zero_cnt_kernel<<<nthr_grid, 256>>>();
}

// round 6
// speedup vs baseline: 2.7881x; 1.0455x over previous
#include <cuda_runtime.h>
#include <cuda_fp16.h>

namespace {

constexpr int N  = 50000;
constexpr int E  = 1600000;
constexpr int IN = 512;
constexpr int H  = 128;
constexpr int C  = 2;
constexpr int G  = 8;
constexpr int NB_SCAN = (N + 255) / 256;

// ---- scratch (static device arrays; zero-initialized at load) ----
__device__ __half g_hs [(size_t)N * H];  // raw gemm output (UNscaled), fp16
__device__ float  g_h  [(size_t)N * H];  // layer output (post aggregation+relu)
__device__ float  g_dinv[N];
__device__ int    g_cnt [N];             // in-degree counts (re-zeroed by scanCD)
__device__ int    g_incl[N];
__device__ int    g_bsum[256];
__device__ int    g_boff[256];
__device__ int    g_rowptr[N + 1];
__device__ int    g_cursor[N];
__device__ int    g_adj[E];
__device__ float  g_pool[G * H];
__device__ float  g_cntf[G];

// ======================= CSR build =======================

__global__ void count_kernel(const int* __restrict__ dst) {
    int e = blockIdx.x * blockDim.x + threadIdx.x;
    if (e < E) atomicAdd(&g_cnt[dst[e]], 1);
}

__global__ void scanA_kernel() {
    __shared__ int sm[256];
    int t = threadIdx.x;
    int i = blockIdx.x * 256 + t;
    int v = (i < N) ? g_cnt[i] : 0;
    sm[t] = v;
    __syncthreads();
    #pragma unroll
    for (int off = 1; off < 256; off <<= 1) {
        int u = (t >= off) ? sm[t - off] : 0;
        __syncthreads();
        sm[t] += u;
        __syncthreads();
    }
    if (i < N) g_incl[i] = sm[t];
    if (t == 255) g_bsum[blockIdx.x] = sm[255];
}

__global__ void scanB_kernel() {
    __shared__ int sm[256];
    int t = threadIdx.x;
    int v = (t < NB_SCAN) ? g_bsum[t] : 0;
    sm[t] = v;
    __syncthreads();
    #pragma unroll
    for (int off = 1; off < 256; off <<= 1) {
        int u = (t >= off) ? sm[t - off] : 0;
        __syncthreads();
        sm[t] += u;
        __syncthreads();
    }
    g_boff[t] = sm[t] - v;   // exclusive
}

// rowptr[i+1], cursor[i]=rowptr[i], dinv[i]; then zero g_cnt for the next call.
__global__ void scanCD_kernel() {
    int i = blockIdx.x * blockDim.x + threadIdx.x;
    if (i < N) {
        int c = g_cnt[i];
        int inc = g_incl[i] + g_boff[i >> 8];
        g_rowptr[i + 1] = inc;
        g_cursor[i] = inc - c;
        g_dinv[i] = rsqrtf((float)c + 1.0f);
        g_cnt[i] = 0;
        if (i == 0) g_rowptr[0] = 0;
    }
}

__global__ void fill_kernel(const int* __restrict__ src, const int* __restrict__ dst) {
    int e = blockIdx.x * blockDim.x + threadIdx.x;
    if (e < E) {
        int d = dst[e];
        int pos = atomicAdd(&g_cursor[d], 1);
        g_adj[pos] = src[e];
    }
}

// ======================= tf32 tensor-core GEMM =======================
// hs[r, 0:128] = half( A[r,:] @ W )   (unscaled — dinv applied in agg)

__device__ __forceinline__ void mma_tf32(float* d, const unsigned* a, const unsigned* b) {
    asm volatile("mma.sync.aligned.m16n8k8.row.col.f32.tf32.tf32.f32 "
        "{%0,%1,%2,%3}, {%4,%5,%6,%7}, {%8,%9}, {%0,%1,%2,%3};"
        : "+f"(d[0]), "+f"(d[1]), "+f"(d[2]), "+f"(d[3])
        : "r"(a[0]), "r"(a[1]), "r"(a[2]), "r"(a[3]), "r"(b[0]), "r"(b[1]));
}

__device__ __forceinline__ void cp16(void* smem_dst, const void* gmem_src, int src_bytes) {
    unsigned sa = (unsigned)__cvta_generic_to_shared(smem_dst);
    asm volatile("cp.async.cg.shared.global [%0], [%1], 16, %2;"
                 :: "r"(sa), "l"(gmem_src), "r"(src_bytes) : "memory");
}
__device__ __forceinline__ void cp_commit() {
    asm volatile("cp.async.commit_group;" ::: "memory");
}
template <int Nw>
__device__ __forceinline__ void cp_wait() {
    asm volatile("cp.async.wait_group %0;" :: "n"(Nw) : "memory");
}

__device__ __forceinline__ unsigned rtf(float f) {
    return __float_as_uint(f) + 0x1000u;   // rn-to-tf32 bit trick
}

constexpr int APAD = 36;
constexpr int BPAD = 136;
constexpr int ASZ  = 2 * 256 * APAD;
constexpr int BSZ  = 2 * 32 * BPAD;
constexpr size_t GEMM_SMEM = (size_t)(ASZ + BSZ) * 4;

template <int K>
__global__ void __launch_bounds__(256)
gemm_cp(const float* __restrict__ A, const float* __restrict__ W,
        __half* __restrict__ hs) {
    constexpr int BK = 32;
    constexpr int STAGES = K / BK;

    extern __shared__ float smem[];
    float* As = smem;
    float* Bs = smem + ASZ;

    const int tid  = threadIdx.x;
    const int lane = tid & 31;
    const int wid  = tid >> 5;
    const int wm   = wid >> 1;
    const int wn   = wid & 1;
    const int bm   = blockIdx.x * 256;

    auto AS = [&](int b, int r, int c) -> float& { return As[b * (256 * APAD) + r * APAD + c]; };
    auto BS = [&](int b, int k, int n) -> float& { return Bs[b * (32 * BPAD) + k * BPAD + n]; };

    auto issue = [&](int s, int buf) {
        const int k0 = s * BK;
        #pragma unroll
        for (int i = 0; i < 2; i++) {
            int r = (tid >> 1) + i * 128;
            int gr = bm + r;
            int sz = (gr < N) ? 16 : 0;
            const float* srow = A + (size_t)gr * K + k0;
            #pragma unroll
            for (int j = 0; j < 4; j++) {
                int ch = (tid & 1) + 2 * j;
                cp16(&AS(buf, r, ch * 4), srow + ch * 4, sz);
            }
        }
        {
            int k = tid >> 3;
            const float* srow = W + (size_t)(k0 + k) * H;
            #pragma unroll
            for (int j = 0; j < 4; j++) {
                int ch = (tid & 7) + 8 * j;
                cp16(&BS(buf, k, ch * 4), srow + ch * 4, 16);
            }
        }
        cp_commit();
    };

    float acc[4][8][4];
    #pragma unroll
    for (int i = 0; i < 4; i++)
        #pragma unroll
        for (int j = 0; j < 8; j++)
            #pragma unroll
            for (int r = 0; r < 4; r++) acc[i][j][r] = 0.f;

    const int gid = lane >> 2;
    const int cid = lane & 3;

    auto compute = [&](int buf) {
        #pragma unroll
        for (int ks = 0; ks < 4; ks++) {
            const int c0 = ks * 8 + cid;
            unsigned af[4][4];
            #pragma unroll
            for (int mt = 0; mt < 4; mt++) {
                int r = wm * 64 + mt * 16 + gid;
                af[mt][0] = rtf(AS(buf, r,     c0));
                af[mt][1] = rtf(AS(buf, r + 8, c0));
                af[mt][2] = rtf(AS(buf, r,     c0 + 4));
                af[mt][3] = rtf(AS(buf, r + 8, c0 + 4));
            }
            unsigned bf[8][2];
            #pragma unroll
            for (int nt = 0; nt < 8; nt++) {
                int n = wn * 64 + nt * 8 + gid;
                bf[nt][0] = rtf(BS(buf, ks * 8 + cid,     n));
                bf[nt][1] = rtf(BS(buf, ks * 8 + cid + 4, n));
            }
            #pragma unroll
            for (int mt = 0; mt < 4; mt++)
                #pragma unroll
                for (int nt = 0; nt < 8; nt++)
                    mma_tf32(acc[mt][nt], af[mt], bf[nt]);
        }
    };

    issue(0, 0);
    for (int s = 0; s < STAGES; s++) {
        if (s + 1 < STAGES) {
            issue(s + 1, (s + 1) & 1);
            cp_wait<1>();
        } else {
            cp_wait<0>();
        }
        __syncthreads();
        compute(s & 1);
        __syncthreads();
    }

    #pragma unroll
    for (int mt = 0; mt < 4; mt++) {
        #pragma unroll
        for (int half = 0; half < 2; half++) {
            int r = bm + wm * 64 + mt * 16 + gid + half * 8;
            if (r < N) {
                #pragma unroll
                for (int nt = 0; nt < 8; nt++) {
                    int c = wn * 64 + nt * 8 + cid * 2;
                    __half2 v = __floats2half2_rn(acc[mt][nt][half * 2],
                                                  acc[mt][nt][half * 2 + 1]);
                    *reinterpret_cast<__half2*>(hs + (size_t)r * H + c) = v;
                }
            }
        }
    }
}

// ======================= CSR aggregation =======================
// warp per node: h[d,:] = relu(dinv[d] * (hs[d,:]*dinv[d] + sum_s hs[s,:]*dinv[s]) + b)
__device__ __forceinline__ void acc_row(float4& acc, uint2 u, float sc) {
    float2 f0 = __half22float2(*reinterpret_cast<__half2*>(&u.x));
    float2 f1 = __half22float2(*reinterpret_cast<__half2*>(&u.y));
    acc.x = fmaf(f0.x, sc, acc.x);
    acc.y = fmaf(f0.y, sc, acc.y);
    acc.z = fmaf(f1.x, sc, acc.z);
    acc.w = fmaf(f1.y, sc, acc.w);
}

__global__ void __launch_bounds__(256)
agg_kernel(const __half* __restrict__ hs, const float* __restrict__ bias,
           float* __restrict__ h) {
    int w = (blockIdx.x * 256 + threadIdx.x) >> 5;
    if (w >= N) return;
    int lane = threadIdx.x & 31;
    const uint2* hs2 = reinterpret_cast<const uint2*>(hs);

    int beg = __ldg(&g_rowptr[w]);
    int end = __ldg(&g_rowptr[w + 1]);
    float di = g_dinv[w];

    float4 acc = make_float4(0.f, 0.f, 0.f, 0.f);
    acc_row(acc, __ldg(&hs2[(size_t)w * 32 + lane]), di);   // self term

    int e = beg;
    for (; e + 8 <= end; e += 8) {
        int s[8];
        #pragma unroll
        for (int j = 0; j < 8; j++) s[j] = __ldg(&g_adj[e + j]);
        uint2 v[8];
        #pragma unroll
        for (int j = 0; j < 8; j++) v[j] = __ldg(&hs2[(size_t)s[j] * 32 + lane]);
        #pragma unroll
        for (int j = 0; j < 8; j++) acc_row(acc, v[j], g_dinv[s[j]]);
    }
    for (; e < end; e++) {
        int s0 = __ldg(&g_adj[e]);
        acc_row(acc, __ldg(&hs2[(size_t)s0 * 32 + lane]), g_dinv[s0]);
    }

    float4 bb = __ldg(&reinterpret_cast<const float4*>(bias)[lane]);
    float4 r;
    r.x = fmaxf(fmaf(di, acc.x, bb.x), 0.f);
    r.y = fmaxf(fmaf(di, acc.y, bb.y), 0.f);
    r.z = fmaxf(fmaf(di, acc.z, bb.z), 0.f);
    r.w = fmaxf(fmaf(di, acc.w, bb.w), 0.f);
    reinterpret_cast<float4*>(h)[(size_t)w * 32 + lane] = r;
}

// ======================= pooling + head =======================

__global__ void zero_pool_kernel() {
    int i = blockIdx.x * blockDim.x + threadIdx.x;
    if (i < G * H) g_pool[i] = 0.f;
    if (i < G) g_cntf[i] = 0.f;
}

__global__ void __launch_bounds__(256)
pool_kernel(const int* __restrict__ batch, const float* __restrict__ h) {
    __shared__ float acc[G * H];
    __shared__ float cnt[G];
    int tid = threadIdx.x;
    for (int i = tid; i < G * H; i += 256) acc[i] = 0.f;
    if (tid < G) cnt[tid] = 0.f;
    __syncthreads();

    int nodes_per_block = (N + gridDim.x - 1) / gridDim.x;
    int n0 = blockIdx.x * nodes_per_block;
    int n1 = min(n0 + nodes_per_block, N);
    int warp = tid >> 5, lane = tid & 31;

    for (int n = n0 + warp; n < n1; n += 8) {
        int g = batch[n];
        #pragma unroll
        for (int j = 0; j < 4; j++) {
            float v = h[(size_t)n * H + lane + j * 32];
            atomicAdd(&acc[g * H + lane + j * 32], v);
        }
        if (lane == 0) atomicAdd(&cnt[g], 1.0f);
    }
    __syncthreads();

    for (int i = tid; i < G * H; i += 256)
        if (acc[i] != 0.f) atomicAdd(&g_pool[i], acc[i]);
    if (tid < G && cnt[tid] != 0.f) atomicAdd(&g_cntf[tid], cnt[tid]);
}

__global__ void head_kernel(const float* __restrict__ Wlin, const float* __restrict__ blin,
                            float* __restrict__ out) {
    int warp = threadIdx.x >> 5, lane = threadIdx.x & 31;
    if (warp >= G * C) return;
    int g = warp >> 1, c = warp & 1;
    float s = 0.f;
    for (int d = lane; d < H; d += 32)
        s += g_pool[g * H + d] * Wlin[d * C + c];
    #pragma unroll
    for (int o = 16; o; o >>= 1) s += __shfl_xor_sync(0xffffffff, s, o);
    if (lane == 0) out[g * C + c] = s / fmaxf(g_cntf[g], 1.0f) + blin[c];
}

} // namespace

extern "C" void kernel_launch(void* const* d_in, const int* in_sizes, int n_in,
                              void* d_out, int out_size) {
    const float* x    = (const float*)d_in[0];
    const int*   ei   = (const int*)  d_in[1];
    const int*   bat  = (const int*)  d_in[2];
    const float* W1   = (const float*)d_in[3];
    const float* b1   = (const float*)d_in[4];
    const float* W2   = (const float*)d_in[5];
    const float* b2   = (const float*)d_in[6];
    const float* Wlin = (const float*)d_in[7];
    const float* blin = (const float*)d_in[8];
    float* out = (float*)d_out;
    const int* src = ei;
    const int* dst = ei + E;

    __half* p_hs;
    float *p_h;
    cudaGetSymbolAddress((void**)&p_hs, g_hs);
    cudaGetSymbolAddress((void**)&p_h,  g_h);

    cudaFuncSetAttribute(gemm_cp<IN>, cudaFuncAttributeMaxDynamicSharedMemorySize, (int)GEMM_SMEM);
    cudaFuncSetAttribute(gemm_cp<H>,  cudaFuncAttributeMaxDynamicSharedMemorySize, (int)GEMM_SMEM);

    // One side stream + fork/join events, created once (outside graph capture:
    // the first call is the uncaptured correctness run).
    static cudaStream_t s2 = nullptr;
    static cudaEvent_t ev_fork = nullptr, ev_join = nullptr;
    if (!s2) {
        cudaStreamCreateWithFlags(&s2, cudaStreamNonBlocking);
        cudaEventCreateWithFlags(&ev_fork, cudaEventDisableTiming);
        cudaEventCreateWithFlags(&ev_join, cudaEventDisableTiming);
    }

    const int gemm_grid = (N + 255) / 256;
    const int agg_grid  = (N * 32 + 255) / 256;
    const int nthr_grid = (N + 255) / 256;
    const int e_grid    = (E + 255) / 256;

    // ---- fork: CSR build on side stream, gemm1 on main stream ----
    cudaEventRecord(ev_fork, 0);
    cudaStreamWaitEvent(s2, ev_fork, 0);

    count_kernel<<<e_grid, 256, 0, s2>>>(dst);
    scanA_kernel<<<NB_SCAN, 256, 0, s2>>>();
    scanB_kernel<<<1, 256, 0, s2>>>();
    scanCD_kernel<<<nthr_grid, 256, 0, s2>>>();
    fill_kernel<<<e_grid, 256, 0, s2>>>(src, dst);
    cudaEventRecord(ev_join, s2);

    gemm_cp<IN><<<gemm_grid, 256, GEMM_SMEM>>>(x, W1, p_hs);   // main stream, concurrent

    // ---- join ----
    cudaStreamWaitEvent(0, ev_join, 0);

    // ---- layer 1 agg, layer 2, pool, head (main stream) ----
    agg_kernel<<<agg_grid, 256>>>(p_hs, b1, p_h);
    gemm_cp<H><<<gemm_grid, 256, GEMM_SMEM>>>(p_h, W2, p_hs);
    agg_kernel<<<agg_grid, 256>>>(p_hs, b2, p_h);

    zero_pool_kernel<<<(G * H + 255) / 256, 256>>>();
    pool_kernel<<<200, 256>>>(bat, p_h);
    head_kernel<<<1, G * C * 32>>>(Wlin, blin, out);
}

// round 8
// speedup vs baseline: 2.8495x; 1.0220x over previous
#include <cuda_runtime.h>
#include <cuda_fp16.h>

namespace {

constexpr int N  = 50000;
constexpr int E  = 1600000;
constexpr int IN = 512;
constexpr int H  = 128;
constexpr int C  = 2;
constexpr int G  = 8;
constexpr int NB_SCAN = (N + 255) / 256;

// ---- scratch (static device arrays; zero-initialized at load) ----
__device__ __half g_hs [(size_t)N * H];  // raw gemm output (UNscaled), fp16
__device__ float  g_h  [(size_t)N * H];  // layer output (post aggregation+relu)
__device__ float  g_dinv[N];
__device__ int    g_cnt [N];             // in-degree counts (re-zeroed by scanCD)
__device__ int    g_incl[N];
__device__ int    g_bsum[256];
__device__ int    g_boff[256];
__device__ int    g_rowptr[N + 1];
__device__ int    g_cursor[N];
__device__ int    g_adj[E];
__device__ float  g_pool[G * H];
__device__ float  g_cntf[G];

// ======================= CSR build =======================

__global__ void count_kernel(const int* __restrict__ dst) {
    int e = blockIdx.x * blockDim.x + threadIdx.x;
    if (e < E) atomicAdd(&g_cnt[dst[e]], 1);
}

__global__ void scanA_kernel() {
    __shared__ int sm[256];
    int t = threadIdx.x;
    int i = blockIdx.x * 256 + t;
    int v = (i < N) ? g_cnt[i] : 0;
    sm[t] = v;
    __syncthreads();
    #pragma unroll
    for (int off = 1; off < 256; off <<= 1) {
        int u = (t >= off) ? sm[t - off] : 0;
        __syncthreads();
        sm[t] += u;
        __syncthreads();
    }
    if (i < N) g_incl[i] = sm[t];
    if (t == 255) g_bsum[blockIdx.x] = sm[255];
}

__global__ void scanB_kernel() {
    __shared__ int sm[256];
    int t = threadIdx.x;
    int v = (t < NB_SCAN) ? g_bsum[t] : 0;
    sm[t] = v;
    __syncthreads();
    #pragma unroll
    for (int off = 1; off < 256; off <<= 1) {
        int u = (t >= off) ? sm[t - off] : 0;
        __syncthreads();
        sm[t] += u;
        __syncthreads();
    }
    g_boff[t] = sm[t] - v;   // exclusive
}

// rowptr[i+1], cursor[i]=rowptr[i], dinv[i]; then zero g_cnt for the next call.
__global__ void scanCD_kernel() {
    int i = blockIdx.x * blockDim.x + threadIdx.x;
    if (i < N) {
        int c = g_cnt[i];
        int inc = g_incl[i] + g_boff[i >> 8];
        g_rowptr[i + 1] = inc;
        g_cursor[i] = inc - c;
        g_dinv[i] = rsqrtf((float)c + 1.0f);
        g_cnt[i] = 0;
        if (i == 0) g_rowptr[0] = 0;
    }
}

__global__ void fill_kernel(const int* __restrict__ src, const int* __restrict__ dst) {
    int e = blockIdx.x * blockDim.x + threadIdx.x;
    if (e < E) {
        int d = dst[e];
        int pos = atomicAdd(&g_cursor[d], 1);
        g_adj[pos] = src[e];
    }
}

// ======================= tf32 tensor-core GEMM =======================
// hs[r, 0:128] = half( A[r,:] @ W )   (unscaled — dinv applied in agg)
// Block tile 256x128, 8 warps (4x2), warp tile 64x64, BK=32,
// 3-stage cp.async ring, ONE __syncthreads per stage.

__device__ __forceinline__ void mma_tf32(float* d, const unsigned* a, const unsigned* b) {
    asm volatile("mma.sync.aligned.m16n8k8.row.col.f32.tf32.tf32.f32 "
        "{%0,%1,%2,%3}, {%4,%5,%6,%7}, {%8,%9}, {%0,%1,%2,%3};"
        : "+f"(d[0]), "+f"(d[1]), "+f"(d[2]), "+f"(d[3])
        : "r"(a[0]), "r"(a[1]), "r"(a[2]), "r"(a[3]), "r"(b[0]), "r"(b[1]));
}

__device__ __forceinline__ void cp16(void* smem_dst, const void* gmem_src, int src_bytes) {
    unsigned sa = (unsigned)__cvta_generic_to_shared(smem_dst);
    asm volatile("cp.async.cg.shared.global [%0], [%1], 16, %2;"
                 :: "r"(sa), "l"(gmem_src), "r"(src_bytes) : "memory");
}
__device__ __forceinline__ void cp_commit() {
    asm volatile("cp.async.commit_group;" ::: "memory");
}
template <int Nw>
__device__ __forceinline__ void cp_wait() {
    asm volatile("cp.async.wait_group %0;" :: "n"(Nw) : "memory");
}

__device__ __forceinline__ unsigned rtf(float f) {
    return __float_as_uint(f) + 0x1000u;   // rn-to-tf32 bit trick
}

constexpr int APAD = 36;
constexpr int BPAD = 136;
constexpr int ASTG = 256 * APAD;           // floats per A stage
constexpr int BSTG = 32 * BPAD;            // floats per B stage
constexpr size_t GEMM_SMEM = (size_t)(3 * ASTG + 3 * BSTG) * 4;   // ~163 KB

template <int K>
__global__ void __launch_bounds__(256)
gemm_cp(const float* __restrict__ A, const float* __restrict__ W,
        __half* __restrict__ hs) {
    constexpr int BK = 32;
    constexpr int STAGES = K / BK;

    extern __shared__ float smem[];
    float* As = smem;               // [3][256][APAD]
    float* Bs = smem + 3 * ASTG;    // [3][32][BPAD]

    const int tid  = threadIdx.x;
    const int lane = tid & 31;
    const int wid  = tid >> 5;
    const int wm   = wid >> 1;
    const int wn   = wid & 1;
    const int bm   = blockIdx.x * 256;

    auto AS = [&](int b, int r, int c) -> float& { return As[b * ASTG + r * APAD + c]; };
    auto BS = [&](int b, int k, int n) -> float& { return Bs[b * BSTG + k * BPAD + n]; };

    auto issue = [&](int s) {
        const int buf = s % 3;
        const int k0 = s * BK;
        #pragma unroll
        for (int i = 0; i < 2; i++) {
            int r = (tid >> 1) + i * 128;
            int gr = bm + r;
            int sz = (gr < N) ? 16 : 0;
            const float* srow = A + (size_t)gr * K + k0;
            #pragma unroll
            for (int j = 0; j < 4; j++) {
                int ch = (tid & 1) + 2 * j;
                cp16(&AS(buf, r, ch * 4), srow + ch * 4, sz);
            }
        }
        {
            int k = tid >> 3;
            const float* srow = W + (size_t)(k0 + k) * H;
            #pragma unroll
            for (int j = 0; j < 4; j++) {
                int ch = (tid & 7) + 8 * j;
                cp16(&BS(buf, k, ch * 4), srow + ch * 4, 16);
            }
        }
        cp_commit();
    };

    float acc[4][8][4];
    #pragma unroll
    for (int i = 0; i < 4; i++)
        #pragma unroll
        for (int j = 0; j < 8; j++)
            #pragma unroll
            for (int r = 0; r < 4; r++) acc[i][j][r] = 0.f;

    const int gid = lane >> 2;
    const int cid = lane & 3;

    auto compute = [&](int s) {
        const int buf = s % 3;
        #pragma unroll
        for (int ks = 0; ks < 4; ks++) {
            const int c0 = ks * 8 + cid;
            unsigned af[4][4];
            #pragma unroll
            for (int mt = 0; mt < 4; mt++) {
                int r = wm * 64 + mt * 16 + gid;
                af[mt][0] = rtf(AS(buf, r,     c0));
                af[mt][1] = rtf(AS(buf, r + 8, c0));
                af[mt][2] = rtf(AS(buf, r,     c0 + 4));
                af[mt][3] = rtf(AS(buf, r + 8, c0 + 4));
            }
            unsigned bf[8][2];
            #pragma unroll
            for (int nt = 0; nt < 8; nt++) {
                int n = wn * 64 + nt * 8 + gid;
                bf[nt][0] = rtf(BS(buf, ks * 8 + cid,     n));
                bf[nt][1] = rtf(BS(buf, ks * 8 + cid + 4, n));
            }
            #pragma unroll
            for (int mt = 0; mt < 4; mt++)
                #pragma unroll
                for (int nt = 0; nt < 8; nt++)
                    mma_tf32(acc[mt][nt], af[mt], bf[nt]);
        }
    };

    // 3-stage ring: wait -> sync -> issue(s+2) -> compute(s).
    // After the sync, all warps finished compute(s-1), so buffer (s+2)%3
    // (== (s-1)%3) is free for the new cp.async writes.
    issue(0);
    if (STAGES > 1) issue(1);
    for (int s = 0; s < STAGES; s++) {
        if (s + 2 < STAGES) cp_wait<1>(); else cp_wait<0>();
        __syncthreads();
        if (s + 2 < STAGES) issue(s + 2);
        compute(s);
    }

    #pragma unroll
    for (int mt = 0; mt < 4; mt++) {
        #pragma unroll
        for (int half = 0; half < 2; half++) {
            int r = bm + wm * 64 + mt * 16 + gid + half * 8;
            if (r < N) {
                #pragma unroll
                for (int nt = 0; nt < 8; nt++) {
                    int c = wn * 64 + nt * 8 + cid * 2;
                    __half2 v = __floats2half2_rn(acc[mt][nt][half * 2],
                                                  acc[mt][nt][half * 2 + 1]);
                    *reinterpret_cast<__half2*>(hs + (size_t)r * H + c) = v;
                }
            }
        }
    }
}

// ======================= CSR aggregation =======================
__device__ __forceinline__ void acc_row(float4& acc, uint2 u, float sc) {
    float2 f0 = __half22float2(*reinterpret_cast<__half2*>(&u.x));
    float2 f1 = __half22float2(*reinterpret_cast<__half2*>(&u.y));
    acc.x = fmaf(f0.x, sc, acc.x);
    acc.y = fmaf(f0.y, sc, acc.y);
    acc.z = fmaf(f1.x, sc, acc.z);
    acc.w = fmaf(f1.y, sc, acc.w);
}

__global__ void __launch_bounds__(256)
agg_kernel(const __half* __restrict__ hs, const float* __restrict__ bias,
           float* __restrict__ h) {
    int w = (blockIdx.x * 256 + threadIdx.x) >> 5;
    if (w >= N) return;
    int lane = threadIdx.x & 31;
    const uint2* hs2 = reinterpret_cast<const uint2*>(hs);

    int beg = __ldg(&g_rowptr[w]);
    int end = __ldg(&g_rowptr[w + 1]);
    float di = g_dinv[w];

    float4 acc = make_float4(0.f, 0.f, 0.f, 0.f);
    acc_row(acc, __ldg(&hs2[(size_t)w * 32 + lane]), di);   // self term

    int e = beg;
    for (; e + 8 <= end; e += 8) {
        int s[8];
        #pragma unroll
        for (int j = 0; j < 8; j++) s[j] = __ldg(&g_adj[e + j]);
        uint2 v[8];
        #pragma unroll
        for (int j = 0; j < 8; j++) v[j] = __ldg(&hs2[(size_t)s[j] * 32 + lane]);
        #pragma unroll
        for (int j = 0; j < 8; j++) acc_row(acc, v[j], g_dinv[s[j]]);
    }
    for (; e < end; e++) {
        int s0 = __ldg(&g_adj[e]);
        acc_row(acc, __ldg(&hs2[(size_t)s0 * 32 + lane]), g_dinv[s0]);
    }

    float4 bb = __ldg(&reinterpret_cast<const float4*>(bias)[lane]);
    float4 r;
    r.x = fmaxf(fmaf(di, acc.x, bb.x), 0.f);
    r.y = fmaxf(fmaf(di, acc.y, bb.y), 0.f);
    r.z = fmaxf(fmaf(di, acc.z, bb.z), 0.f);
    r.w = fmaxf(fmaf(di, acc.w, bb.w), 0.f);
    reinterpret_cast<float4*>(h)[(size_t)w * 32 + lane] = r;
}

// ======================= pooling + head =======================

__global__ void zero_pool_kernel() {
    int i = blockIdx.x * blockDim.x + threadIdx.x;
    if (i < G * H) g_pool[i] = 0.f;
    if (i < G) g_cntf[i] = 0.f;
}

__global__ void __launch_bounds__(256)
pool_kernel(const int* __restrict__ batch, const float* __restrict__ h) {
    __shared__ float acc[G * H];
    __shared__ float cnt[G];
    int tid = threadIdx.x;
    for (int i = tid; i < G * H; i += 256) acc[i] = 0.f;
    if (tid < G) cnt[tid] = 0.f;
    __syncthreads();

    int nodes_per_block = (N + gridDim.x - 1) / gridDim.x;
    int n0 = blockIdx.x * nodes_per_block;
    int n1 = min(n0 + nodes_per_block, N);
    int warp = tid >> 5, lane = tid & 31;

    for (int n = n0 + warp; n < n1; n += 8) {
        int g = batch[n];
        #pragma unroll
        for (int j = 0; j < 4; j++) {
            float v = h[(size_t)n * H + lane + j * 32];
            atomicAdd(&acc[g * H + lane + j * 32], v);
        }
        if (lane == 0) atomicAdd(&cnt[g], 1.0f);
    }
    __syncthreads();

    for (int i = tid; i < G * H; i += 256)
        if (acc[i] != 0.f) atomicAdd(&g_pool[i], acc[i]);
    if (tid < G && cnt[tid] != 0.f) atomicAdd(&g_cntf[tid], cnt[tid]);
}

__global__ void head_kernel(const float* __restrict__ Wlin, const float* __restrict__ blin,
                            float* __restrict__ out) {
    int warp = threadIdx.x >> 5, lane = threadIdx.x & 31;
    if (warp >= G * C) return;
    int g = warp >> 1, c = warp & 1;
    float s = 0.f;
    for (int d = lane; d < H; d += 32)
        s += g_pool[g * H + d] * Wlin[d * C + c];
    #pragma unroll
    for (int o = 16; o; o >>= 1) s += __shfl_xor_sync(0xffffffff, s, o);
    if (lane == 0) out[g * C + c] = s / fmaxf(g_cntf[g], 1.0f) + blin[c];
}

} // namespace

extern "C" void kernel_launch(void* const* d_in, const int* in_sizes, int n_in,
                              void* d_out, int out_size) {
    const float* x    = (const float*)d_in[0];
    const int*   ei   = (const int*)  d_in[1];
    const int*   bat  = (const int*)  d_in[2];
    const float* W1   = (const float*)d_in[3];
    const float* b1   = (const float*)d_in[4];
    const float* W2   = (const float*)d_in[5];
    const float* b2   = (const float*)d_in[6];
    const float* Wlin = (const float*)d_in[7];
    const float* blin = (const float*)d_in[8];
    float* out = (float*)d_out;
    const int* src = ei;
    const int* dst = ei + E;

    __half* p_hs;
    float *p_h;
    cudaGetSymbolAddress((void**)&p_hs, g_hs);
    cudaGetSymbolAddress((void**)&p_h,  g_h);

    cudaFuncSetAttribute(gemm_cp<IN>, cudaFuncAttributeMaxDynamicSharedMemorySize, (int)GEMM_SMEM);
    cudaFuncSetAttribute(gemm_cp<H>,  cudaFuncAttributeMaxDynamicSharedMemorySize, (int)GEMM_SMEM);

    static cudaStream_t s2 = nullptr;
    static cudaEvent_t ev_fork = nullptr, ev_join = nullptr;
    if (!s2) {
        cudaStreamCreateWithFlags(&s2, cudaStreamNonBlocking);
        cudaEventCreateWithFlags(&ev_fork, cudaEventDisableTiming);
        cudaEventCreateWithFlags(&ev_join, cudaEventDisableTiming);
    }

    const int gemm_grid = (N + 255) / 256;
    const int agg_grid  = (N * 32 + 255) / 256;
    const int nthr_grid = (N + 255) / 256;
    const int e_grid    = (E + 255) / 256;

    // ---- fork: CSR build on side stream, gemm1 on main stream ----
    cudaEventRecord(ev_fork, 0);
    cudaStreamWaitEvent(s2, ev_fork, 0);

    // Enqueue order chosen so gemm1 is the 4th kernel (ncu window index 3).
    count_kernel<<<e_grid, 256, 0, s2>>>(dst);                 // 0
    scanA_kernel<<<NB_SCAN, 256, 0, s2>>>();                   // 1
    scanB_kernel<<<1, 256, 0, s2>>>();                         // 2
    gemm_cp<IN><<<gemm_grid, 256, GEMM_SMEM>>>(x, W1, p_hs);   // 3 (main stream)
    scanCD_kernel<<<nthr_grid, 256, 0, s2>>>();                // 4
    fill_kernel<<<e_grid, 256, 0, s2>>>(src, dst);             // 5
    cudaEventRecord(ev_join, s2);

    // ---- join ----
    cudaStreamWaitEvent(0, ev_join, 0);

    // ---- layer 1 agg, layer 2, pool, head (main stream) ----
    agg_kernel<<<agg_grid, 256>>>(p_hs, b1, p_h);
    gemm_cp<H><<<gemm_grid, 256, GEMM_SMEM>>>(p_h, W2, p_hs);
    agg_kernel<<<agg_grid, 256>>>(p_hs, b2, p_h);

    zero_pool_kernel<<<(G * H + 255) / 256, 256>>>();
    pool_kernel<<<200, 256>>>(bat, p_h);
    head_kernel<<<1, G * C * 32>>>(Wlin, blin, out);
}

// round 9
// speedup vs baseline: 2.9303x; 1.0284x over previous
#include <cuda_runtime.h>
#include <cuda_fp16.h>

namespace {

constexpr int N  = 50000;
constexpr int E  = 1600000;
constexpr int IN = 512;
constexpr int H  = 128;
constexpr int C  = 2;
constexpr int G  = 8;
constexpr int NB_SCAN = (N + 255) / 256;

// ---- scratch (static device arrays; zero-initialized at load) ----
__device__ __half g_hs [(size_t)N * H];  // raw gemm output (UNscaled), fp16
__device__ float  g_h  [(size_t)N * H];  // layer output (post aggregation+relu)
__device__ float  g_dinv[N];
__device__ int    g_cnt [N];             // in-degree counts (re-zeroed by scanCD)
__device__ int    g_incl[N];
__device__ int    g_bsum[256];
__device__ int    g_boff[256];
__device__ int    g_rowptr[N + 1];
__device__ int    g_cursor[N];
__device__ int    g_adj[E];
__device__ float  g_pool[G * H];
__device__ float  g_cntf[G];

// ======================= CSR build =======================

__global__ void count_kernel(const int* __restrict__ dst) {
    int e = blockIdx.x * blockDim.x + threadIdx.x;
    if (e < E) atomicAdd(&g_cnt[dst[e]], 1);
}

__global__ void scanA_kernel() {
    __shared__ int sm[256];
    int t = threadIdx.x;
    int i = blockIdx.x * 256 + t;
    int v = (i < N) ? g_cnt[i] : 0;
    sm[t] = v;
    __syncthreads();
    #pragma unroll
    for (int off = 1; off < 256; off <<= 1) {
        int u = (t >= off) ? sm[t - off] : 0;
        __syncthreads();
        sm[t] += u;
        __syncthreads();
    }
    if (i < N) g_incl[i] = sm[t];
    if (t == 255) g_bsum[blockIdx.x] = sm[255];
}

__global__ void scanB_kernel() {
    __shared__ int sm[256];
    int t = threadIdx.x;
    int v = (t < NB_SCAN) ? g_bsum[t] : 0;
    sm[t] = v;
    __syncthreads();
    #pragma unroll
    for (int off = 1; off < 256; off <<= 1) {
        int u = (t >= off) ? sm[t - off] : 0;
        __syncthreads();
        sm[t] += u;
        __syncthreads();
    }
    g_boff[t] = sm[t] - v;   // exclusive
}

// rowptr[i+1], cursor[i]=rowptr[i], dinv[i]; then zero g_cnt for the next call.
__global__ void scanCD_kernel() {
    int i = blockIdx.x * blockDim.x + threadIdx.x;
    if (i < N) {
        int c = g_cnt[i];
        int inc = g_incl[i] + g_boff[i >> 8];
        g_rowptr[i + 1] = inc;
        g_cursor[i] = inc - c;
        g_dinv[i] = rsqrtf((float)c + 1.0f);
        g_cnt[i] = 0;
        if (i == 0) g_rowptr[0] = 0;
    }
}

__global__ void fill_kernel(const int* __restrict__ src, const int* __restrict__ dst) {
    int e = blockIdx.x * blockDim.x + threadIdx.x;
    if (e < E) {
        int d = dst[e];
        int pos = atomicAdd(&g_cursor[d], 1);
        g_adj[pos] = src[e];
    }
}

// ======================= tf32 tensor-core GEMM =======================
// hs[r, 0:128] = half( A[r,:] @ W )   (unscaled — dinv applied in agg)
// Block tile 128x128, 8 warps (4 wm x 2 wn), warp tile 32x64, BK=32,
// 3-stage cp.async ring, ONE __syncthreads per stage, 2 CTAs/SM.

__device__ __forceinline__ void mma_tf32(float* d, const unsigned* a, const unsigned* b) {
    asm volatile("mma.sync.aligned.m16n8k8.row.col.f32.tf32.tf32.f32 "
        "{%0,%1,%2,%3}, {%4,%5,%6,%7}, {%8,%9}, {%0,%1,%2,%3};"
        : "+f"(d[0]), "+f"(d[1]), "+f"(d[2]), "+f"(d[3])
        : "r"(a[0]), "r"(a[1]), "r"(a[2]), "r"(a[3]), "r"(b[0]), "r"(b[1]));
}

__device__ __forceinline__ void cp16(void* smem_dst, const void* gmem_src, int src_bytes) {
    unsigned sa = (unsigned)__cvta_generic_to_shared(smem_dst);
    asm volatile("cp.async.cg.shared.global [%0], [%1], 16, %2;"
                 :: "r"(sa), "l"(gmem_src), "r"(src_bytes) : "memory");
}
__device__ __forceinline__ void cp_commit() {
    asm volatile("cp.async.commit_group;" ::: "memory");
}
template <int Nw>
__device__ __forceinline__ void cp_wait() {
    asm volatile("cp.async.wait_group %0;" :: "n"(Nw) : "memory");
}

__device__ __forceinline__ unsigned rtf(float f) {
    return __float_as_uint(f) + 0x1000u;   // rn-to-tf32 bit trick
}

constexpr int APAD = 36;
constexpr int BPAD = 136;
constexpr int ASTG = 128 * APAD;           // floats per A stage
constexpr int BSTG = 32 * BPAD;            // floats per B stage
constexpr size_t GEMM_SMEM = (size_t)(3 * ASTG + 3 * BSTG) * 4;   // 105 KB

template <int K>
__global__ void __launch_bounds__(256, 2)
gemm_cp(const float* __restrict__ A, const float* __restrict__ W,
        __half* __restrict__ hs) {
    constexpr int BK = 32;
    constexpr int STAGES = K / BK;

    extern __shared__ float smem[];
    float* As = smem;               // [3][128][APAD]
    float* Bs = smem + 3 * ASTG;    // [3][32][BPAD]

    const int tid  = threadIdx.x;
    const int lane = tid & 31;
    const int wid  = tid >> 5;
    const int wm   = wid >> 1;      // 0..3, 32 rows each
    const int wn   = wid & 1;       // 0..1, 64 cols each
    const int bm   = blockIdx.x * 128;

    auto AS = [&](int b, int r, int c) -> float& { return As[b * ASTG + r * APAD + c]; };
    auto BS = [&](int b, int k, int n) -> float& { return Bs[b * BSTG + k * BPAD + n]; };

    auto issue = [&](int s) {
        const int buf = s % 3;
        const int k0 = s * BK;
        {
            int r = tid >> 1;               // 0..127
            int gr = bm + r;
            int sz = (gr < N) ? 16 : 0;
            const float* srow = A + (size_t)gr * K + k0;
            #pragma unroll
            for (int j = 0; j < 4; j++) {
                int ch = (tid & 1) + 2 * j;
                cp16(&AS(buf, r, ch * 4), srow + ch * 4, sz);
            }
        }
        {
            int k = tid >> 3;               // 0..31
            const float* srow = W + (size_t)(k0 + k) * H;
            #pragma unroll
            for (int j = 0; j < 4; j++) {
                int ch = (tid & 7) + 8 * j;
                cp16(&BS(buf, k, ch * 4), srow + ch * 4, 16);
            }
        }
        cp_commit();
    };

    float acc[2][8][4];
    #pragma unroll
    for (int i = 0; i < 2; i++)
        #pragma unroll
        for (int j = 0; j < 8; j++)
            #pragma unroll
            for (int r = 0; r < 4; r++) acc[i][j][r] = 0.f;

    const int gid = lane >> 2;
    const int cid = lane & 3;

    auto compute = [&](int s) {
        const int buf = s % 3;
        #pragma unroll
        for (int ks = 0; ks < 4; ks++) {
            const int c0 = ks * 8 + cid;
            unsigned af[2][4];
            #pragma unroll
            for (int mt = 0; mt < 2; mt++) {
                int r = wm * 32 + mt * 16 + gid;
                af[mt][0] = rtf(AS(buf, r,     c0));
                af[mt][1] = rtf(AS(buf, r + 8, c0));
                af[mt][2] = rtf(AS(buf, r,     c0 + 4));
                af[mt][3] = rtf(AS(buf, r + 8, c0 + 4));
            }
            unsigned bf[8][2];
            #pragma unroll
            for (int nt = 0; nt < 8; nt++) {
                int n = wn * 64 + nt * 8 + gid;
                bf[nt][0] = rtf(BS(buf, ks * 8 + cid,     n));
                bf[nt][1] = rtf(BS(buf, ks * 8 + cid + 4, n));
            }
            #pragma unroll
            for (int mt = 0; mt < 2; mt++)
                #pragma unroll
                for (int nt = 0; nt < 8; nt++)
                    mma_tf32(acc[mt][nt], af[mt], bf[nt]);
        }
    };

    // 3-stage ring: wait -> sync -> issue(s+2) -> compute(s).
    issue(0);
    if (STAGES > 1) issue(1);
    for (int s = 0; s < STAGES; s++) {
        if (s + 2 < STAGES) cp_wait<1>(); else cp_wait<0>();
        __syncthreads();
        if (s + 2 < STAGES) issue(s + 2);
        compute(s);
    }

    #pragma unroll
    for (int mt = 0; mt < 2; mt++) {
        #pragma unroll
        for (int half = 0; half < 2; half++) {
            int r = bm + wm * 32 + mt * 16 + gid + half * 8;
            if (r < N) {
                #pragma unroll
                for (int nt = 0; nt < 8; nt++) {
                    int c = wn * 64 + nt * 8 + cid * 2;
                    __half2 v = __floats2half2_rn(acc[mt][nt][half * 2],
                                                  acc[mt][nt][half * 2 + 1]);
                    *reinterpret_cast<__half2*>(hs + (size_t)r * H + c) = v;
                }
            }
        }
    }
}

// ======================= CSR aggregation =======================
__device__ __forceinline__ void acc_row(float4& acc, uint2 u, float sc) {
    float2 f0 = __half22float2(*reinterpret_cast<__half2*>(&u.x));
    float2 f1 = __half22float2(*reinterpret_cast<__half2*>(&u.y));
    acc.x = fmaf(f0.x, sc, acc.x);
    acc.y = fmaf(f0.y, sc, acc.y);
    acc.z = fmaf(f1.x, sc, acc.z);
    acc.w = fmaf(f1.y, sc, acc.w);
}

__global__ void __launch_bounds__(256)
agg_kernel(const __half* __restrict__ hs, const float* __restrict__ bias,
           float* __restrict__ h) {
    int w = (blockIdx.x * 256 + threadIdx.x) >> 5;
    if (w >= N) return;
    int lane = threadIdx.x & 31;
    const uint2* hs2 = reinterpret_cast<const uint2*>(hs);

    int beg = __ldg(&g_rowptr[w]);
    int end = __ldg(&g_rowptr[w + 1]);
    float di = g_dinv[w];

    float4 acc = make_float4(0.f, 0.f, 0.f, 0.f);
    acc_row(acc, __ldg(&hs2[(size_t)w * 32 + lane]), di);   // self term

    int e = beg;
    for (; e + 8 <= end; e += 8) {
        int s[8];
        #pragma unroll
        for (int j = 0; j < 8; j++) s[j] = __ldg(&g_adj[e + j]);
        uint2 v[8];
        #pragma unroll
        for (int j = 0; j < 8; j++) v[j] = __ldg(&hs2[(size_t)s[j] * 32 + lane]);
        #pragma unroll
        for (int j = 0; j < 8; j++) acc_row(acc, v[j], g_dinv[s[j]]);
    }
    for (; e < end; e++) {
        int s0 = __ldg(&g_adj[e]);
        acc_row(acc, __ldg(&hs2[(size_t)s0 * 32 + lane]), g_dinv[s0]);
    }

    float4 bb = __ldg(&reinterpret_cast<const float4*>(bias)[lane]);
    float4 r;
    r.x = fmaxf(fmaf(di, acc.x, bb.x), 0.f);
    r.y = fmaxf(fmaf(di, acc.y, bb.y), 0.f);
    r.z = fmaxf(fmaf(di, acc.z, bb.z), 0.f);
    r.w = fmaxf(fmaf(di, acc.w, bb.w), 0.f);
    reinterpret_cast<float4*>(h)[(size_t)w * 32 + lane] = r;
}

// ======================= pooling + head =======================

__global__ void zero_pool_kernel() {
    int i = blockIdx.x * blockDim.x + threadIdx.x;
    if (i < G * H) g_pool[i] = 0.f;
    if (i < G) g_cntf[i] = 0.f;
}

__global__ void __launch_bounds__(256)
pool_kernel(const int* __restrict__ batch, const float* __restrict__ h) {
    __shared__ float acc[G * H];
    __shared__ float cnt[G];
    int tid = threadIdx.x;
    for (int i = tid; i < G * H; i += 256) acc[i] = 0.f;
    if (tid < G) cnt[tid] = 0.f;
    __syncthreads();

    int nodes_per_block = (N + gridDim.x - 1) / gridDim.x;
    int n0 = blockIdx.x * nodes_per_block;
    int n1 = min(n0 + nodes_per_block, N);
    int warp = tid >> 5, lane = tid & 31;

    for (int n = n0 + warp; n < n1; n += 8) {
        int g = batch[n];
        #pragma unroll
        for (int j = 0; j < 4; j++) {
            float v = h[(size_t)n * H + lane + j * 32];
            atomicAdd(&acc[g * H + lane + j * 32], v);
        }
        if (lane == 0) atomicAdd(&cnt[g], 1.0f);
    }
    __syncthreads();

    for (int i = tid; i < G * H; i += 256)
        if (acc[i] != 0.f) atomicAdd(&g_pool[i], acc[i]);
    if (tid < G && cnt[tid] != 0.f) atomicAdd(&g_cntf[tid], cnt[tid]);
}

__global__ void head_kernel(const float* __restrict__ Wlin, const float* __restrict__ blin,
                            float* __restrict__ out) {
    int warp = threadIdx.x >> 5, lane = threadIdx.x & 31;
    if (warp >= G * C) return;
    int g = warp >> 1, c = warp & 1;
    float s = 0.f;
    for (int d = lane; d < H; d += 32)
        s += g_pool[g * H + d] * Wlin[d * C + c];
    #pragma unroll
    for (int o = 16; o; o >>= 1) s += __shfl_xor_sync(0xffffffff, s, o);
    if (lane == 0) out[g * C + c] = s / fmaxf(g_cntf[g], 1.0f) + blin[c];
}

} // namespace

extern "C" void kernel_launch(void* const* d_in, const int* in_sizes, int n_in,
                              void* d_out, int out_size) {
    const float* x    = (const float*)d_in[0];
    const int*   ei   = (const int*)  d_in[1];
    const int*   bat  = (const int*)  d_in[2];
    const float* W1   = (const float*)d_in[3];
    const float* b1   = (const float*)d_in[4];
    const float* W2   = (const float*)d_in[5];
    const float* b2   = (const float*)d_in[6];
    const float* Wlin = (const float*)d_in[7];
    const float* blin = (const float*)d_in[8];
    float* out = (float*)d_out;
    const int* src = ei;
    const int* dst = ei + E;

    __half* p_hs;
    float *p_h;
    cudaGetSymbolAddress((void**)&p_hs, g_hs);
    cudaGetSymbolAddress((void**)&p_h,  g_h);

    cudaFuncSetAttribute(gemm_cp<IN>, cudaFuncAttributeMaxDynamicSharedMemorySize, (int)GEMM_SMEM);
    cudaFuncSetAttribute(gemm_cp<H>,  cudaFuncAttributeMaxDynamicSharedMemorySize, (int)GEMM_SMEM);

    static cudaStream_t s2 = nullptr;
    static cudaEvent_t ev_fork = nullptr, ev_join = nullptr;
    if (!s2) {
        cudaStreamCreateWithFlags(&s2, cudaStreamNonBlocking);
        cudaEventCreateWithFlags(&ev_fork, cudaEventDisableTiming);
        cudaEventCreateWithFlags(&ev_join, cudaEventDisableTiming);
    }

    const int gemm_grid = (N + 127) / 128;       // 391
    const int agg_grid  = (N * 32 + 255) / 256;
    const int nthr_grid = (N + 255) / 256;
    const int e_grid    = (E + 255) / 256;

    // ---- fork: CSR build on side stream, gemm1 on main stream ----
    cudaEventRecord(ev_fork, 0);
    cudaStreamWaitEvent(s2, ev_fork, 0);

    // gemm1 is the 4th enqueued kernel (ncu window index 3).
    count_kernel<<<e_grid, 256, 0, s2>>>(dst);                 // 0
    scanA_kernel<<<NB_SCAN, 256, 0, s2>>>();                   // 1
    scanB_kernel<<<1, 256, 0, s2>>>();                         // 2
    gemm_cp<IN><<<gemm_grid, 256, GEMM_SMEM>>>(x, W1, p_hs);   // 3 (main stream)
    scanCD_kernel<<<nthr_grid, 256, 0, s2>>>();                // 4
    fill_kernel<<<e_grid, 256, 0, s2>>>(src, dst);             // 5
    cudaEventRecord(ev_join, s2);

    // ---- join ----
    cudaStreamWaitEvent(0, ev_join, 0);

    // ---- layer 1 agg, layer 2, pool, head (main stream) ----
    agg_kernel<<<agg_grid, 256>>>(p_hs, b1, p_h);
    gemm_cp<H><<<gemm_grid, 256, GEMM_SMEM>>>(p_h, W2, p_hs);
    agg_kernel<<<agg_grid, 256>>>(p_hs, b2, p_h);

    zero_pool_kernel<<<(G * H + 255) / 256, 256>>>();
    pool_kernel<<<200, 256>>>(bat, p_h);
    head_kernel<<<1, G * C * 32>>>(Wlin, blin, out);
}

// round 11
// speedup vs baseline: 3.4289x; 1.1701x over previous
#include <cuda_runtime.h>
#include <cuda_fp16.h>

namespace {

constexpr int N  = 50000;
constexpr int E  = 1600000;
constexpr int IN = 512;
constexpr int H  = 128;
constexpr int C  = 2;
constexpr int G  = 8;
constexpr int NB_SCAN = (N + 255) / 256;

// ---- scratch (static device arrays; zero-initialized at load) ----
__device__ __half g_hs [(size_t)N * H];  // raw gemm output (UNscaled), fp16
__device__ float  g_h  [(size_t)N * H];  // layer-1 output (post aggregation+relu)
__device__ float  g_dinv[N];
__device__ int    g_cnt [N];             // in-degree counts (re-zeroed by scanCD)
__device__ int    g_incl[N];
__device__ int    g_bsum[256];
__device__ int    g_boff[256];
__device__ int    g_rowptr[N + 1];
__device__ int    g_cursor[N];
__device__ int2   g_adjp[E];             // {src, bits(dinv[src])} grouped by dst
__device__ float  g_pool[G * H];
__device__ float  g_cntf[G];

// ======================= CSR build =======================

__global__ void count_kernel(const int* __restrict__ dst) {
    int e = blockIdx.x * blockDim.x + threadIdx.x;
    if (e < E) atomicAdd(&g_cnt[dst[e]], 1);
}

__global__ void scanA_kernel() {
    __shared__ int sm[256];
    int t = threadIdx.x;
    int i = blockIdx.x * 256 + t;
    int v = (i < N) ? g_cnt[i] : 0;
    sm[t] = v;
    __syncthreads();
    #pragma unroll
    for (int off = 1; off < 256; off <<= 1) {
        int u = (t >= off) ? sm[t - off] : 0;
        __syncthreads();
        sm[t] += u;
        __syncthreads();
    }
    if (i < N) g_incl[i] = sm[t];
    if (t == 255) g_bsum[blockIdx.x] = sm[255];
}

__global__ void scanB_kernel() {
    __shared__ int sm[256];
    int t = threadIdx.x;
    int v = (t < NB_SCAN) ? g_bsum[t] : 0;
    sm[t] = v;
    __syncthreads();
    #pragma unroll
    for (int off = 1; off < 256; off <<= 1) {
        int u = (t >= off) ? sm[t - off] : 0;
        __syncthreads();
        sm[t] += u;
        __syncthreads();
    }
    g_boff[t] = sm[t] - v;   // exclusive
}

// rowptr[i+1], cursor[i]=rowptr[i], dinv[i]; then zero g_cnt for the next call.
__global__ void scanCD_kernel() {
    int i = blockIdx.x * blockDim.x + threadIdx.x;
    if (i < N) {
        int c = g_cnt[i];
        int inc = g_incl[i] + g_boff[i >> 8];
        g_rowptr[i + 1] = inc;
        g_cursor[i] = inc - c;
        g_dinv[i] = rsqrtf((float)c + 1.0f);
        g_cnt[i] = 0;
        if (i == 0) g_rowptr[0] = 0;
    }
}

// Packs {src, dinv[src]} so agg needs only one sequential 8B load per edge.
__global__ void fill_kernel(const int* __restrict__ src, const int* __restrict__ dst) {
    int e = blockIdx.x * blockDim.x + threadIdx.x;
    if (e < E) {
        int s = src[e];
        int d = dst[e];
        int pos = atomicAdd(&g_cursor[d], 1);
        g_adjp[pos] = make_int2(s, __float_as_int(g_dinv[s]));
    }
}

__global__ void zero_pool_kernel() {
    int i = blockIdx.x * blockDim.x + threadIdx.x;
    if (i < G * H) g_pool[i] = 0.f;
    if (i < G) g_cntf[i] = 0.f;
}

// ======================= tf32 tensor-core GEMM =======================
// hs[r, 0:128] = half( A[r,:] @ W )   (unscaled — dinv applied in agg)
// Block tile 128x128, 8 warps (4 wm x 2 wn), warp tile 32x64, BK=32,
// 3-stage cp.async ring, ONE __syncthreads per stage, 2 CTAs/SM.

__device__ __forceinline__ void mma_tf32(float* d, const unsigned* a, const unsigned* b) {
    asm volatile("mma.sync.aligned.m16n8k8.row.col.f32.tf32.tf32.f32 "
        "{%0,%1,%2,%3}, {%4,%5,%6,%7}, {%8,%9}, {%0,%1,%2,%3};"
        : "+f"(d[0]), "+f"(d[1]), "+f"(d[2]), "+f"(d[3])
        : "r"(a[0]), "r"(a[1]), "r"(a[2]), "r"(a[3]), "r"(b[0]), "r"(b[1]));
}

__device__ __forceinline__ void cp16(void* smem_dst, const void* gmem_src, int src_bytes) {
    unsigned sa = (unsigned)__cvta_generic_to_shared(smem_dst);
    asm volatile("cp.async.cg.shared.global [%0], [%1], 16, %2;"
                 :: "r"(sa), "l"(gmem_src), "r"(src_bytes) : "memory");
}
__device__ __forceinline__ void cp_commit() {
    asm volatile("cp.async.commit_group;" ::: "memory");
}
template <int Nw>
__device__ __forceinline__ void cp_wait() {
    asm volatile("cp.async.wait_group %0;" :: "n"(Nw) : "memory");
}

__device__ __forceinline__ unsigned rtf(float f) {
    return __float_as_uint(f) + 0x1000u;   // rn-to-tf32 bit trick
}

constexpr int APAD = 36;
constexpr int BPAD = 136;
constexpr int ASTG = 128 * APAD;
constexpr int BSTG = 32 * BPAD;
constexpr size_t GEMM_SMEM = (size_t)(3 * ASTG + 3 * BSTG) * 4;   // 105 KB

template <int K>
__global__ void __launch_bounds__(256, 2)
gemm_cp(const float* __restrict__ A, const float* __restrict__ W,
        __half* __restrict__ hs) {
    constexpr int BK = 32;
    constexpr int STAGES = K / BK;

    extern __shared__ float smem[];
    float* As = smem;
    float* Bs = smem + 3 * ASTG;

    const int tid  = threadIdx.x;
    const int lane = tid & 31;
    const int wid  = tid >> 5;
    const int wm   = wid >> 1;
    const int wn   = wid & 1;
    const int bm   = blockIdx.x * 128;

    auto AS = [&](int b, int r, int c) -> float& { return As[b * ASTG + r * APAD + c]; };
    auto BS = [&](int b, int k, int n) -> float& { return Bs[b * BSTG + k * BPAD + n]; };

    auto issue = [&](int s) {
        const int buf = s % 3;
        const int k0 = s * BK;
        {
            int r = tid >> 1;
            int gr = bm + r;
            int sz = (gr < N) ? 16 : 0;
            const float* srow = A + (size_t)gr * K + k0;
            #pragma unroll
            for (int j = 0; j < 4; j++) {
                int ch = (tid & 1) + 2 * j;
                cp16(&AS(buf, r, ch * 4), srow + ch * 4, sz);
            }
        }
        {
            int k = tid >> 3;
            const float* srow = W + (size_t)(k0 + k) * H;
            #pragma unroll
            for (int j = 0; j < 4; j++) {
                int ch = (tid & 7) + 8 * j;
                cp16(&BS(buf, k, ch * 4), srow + ch * 4, 16);
            }
        }
        cp_commit();
    };

    float acc[2][8][4];
    #pragma unroll
    for (int i = 0; i < 2; i++)
        #pragma unroll
        for (int j = 0; j < 8; j++)
            #pragma unroll
            for (int r = 0; r < 4; r++) acc[i][j][r] = 0.f;

    const int gid = lane >> 2;
    const int cid = lane & 3;

    auto compute = [&](int s) {
        const int buf = s % 3;
        #pragma unroll
        for (int ks = 0; ks < 4; ks++) {
            const int c0 = ks * 8 + cid;
            unsigned af[2][4];
            #pragma unroll
            for (int mt = 0; mt < 2; mt++) {
                int r = wm * 32 + mt * 16 + gid;
                af[mt][0] = rtf(AS(buf, r,     c0));
                af[mt][1] = rtf(AS(buf, r + 8, c0));
                af[mt][2] = rtf(AS(buf, r,     c0 + 4));
                af[mt][3] = rtf(AS(buf, r + 8, c0 + 4));
            }
            unsigned bf[8][2];
            #pragma unroll
            for (int nt = 0; nt < 8; nt++) {
                int n = wn * 64 + nt * 8 + gid;
                bf[nt][0] = rtf(BS(buf, ks * 8 + cid,     n));
                bf[nt][1] = rtf(BS(buf, ks * 8 + cid + 4, n));
            }
            #pragma unroll
            for (int mt = 0; mt < 2; mt++)
                #pragma unroll
                for (int nt = 0; nt < 8; nt++)
                    mma_tf32(acc[mt][nt], af[mt], bf[nt]);
        }
    };

    issue(0);
    if (STAGES > 1) issue(1);
    for (int s = 0; s < STAGES; s++) {
        if (s + 2 < STAGES) cp_wait<1>(); else cp_wait<0>();
        __syncthreads();
        if (s + 2 < STAGES) issue(s + 2);
        compute(s);
    }

    #pragma unroll
    for (int mt = 0; mt < 2; mt++) {
        #pragma unroll
        for (int half = 0; half < 2; half++) {
            int r = bm + wm * 32 + mt * 16 + gid + half * 8;
            if (r < N) {
                #pragma unroll
                for (int nt = 0; nt < 8; nt++) {
                    int c = wn * 64 + nt * 8 + cid * 2;
                    __half2 v = __floats2half2_rn(acc[mt][nt][half * 2],
                                                  acc[mt][nt][half * 2 + 1]);
                    *reinterpret_cast<__half2*>(hs + (size_t)r * H + c) = v;
                }
            }
        }
    }
}

// ======================= CSR aggregation =======================

__device__ __forceinline__ void acc_row(float4& acc, uint2 u, float sc) {
    float2 f0 = __half22float2(*reinterpret_cast<__half2*>(&u.x));
    float2 f1 = __half22float2(*reinterpret_cast<__half2*>(&u.y));
    acc.x = fmaf(f0.x, sc, acc.x);
    acc.y = fmaf(f0.y, sc, acc.y);
    acc.z = fmaf(f1.x, sc, acc.z);
    acc.w = fmaf(f1.y, sc, acc.w);
}

// Shared row-reduce: returns relu(dinv[w]*acc + bias) for node w's 4 columns.
__device__ __forceinline__ float4 node_row(const uint2* hs2, const float* bias,
                                           int w, int lane) {
    int beg = __ldg(&g_rowptr[w]);
    int end = __ldg(&g_rowptr[w + 1]);
    float di = g_dinv[w];

    float4 acc = make_float4(0.f, 0.f, 0.f, 0.f);
    acc_row(acc, __ldg(&hs2[(size_t)w * 32 + lane]), di);   // self term

    int e = beg;
    for (; e + 8 <= end; e += 8) {
        int2 p[8];
        #pragma unroll
        for (int j = 0; j < 8; j++) p[j] = __ldg(&g_adjp[e + j]);
        uint2 v[8];
        #pragma unroll
        for (int j = 0; j < 8; j++) v[j] = __ldg(&hs2[(size_t)p[j].x * 32 + lane]);
        #pragma unroll
        for (int j = 0; j < 8; j++) acc_row(acc, v[j], __int_as_float(p[j].y));
    }
    for (; e < end; e++) {
        int2 p = __ldg(&g_adjp[e]);
        acc_row(acc, __ldg(&hs2[(size_t)p.x * 32 + lane]), __int_as_float(p.y));
    }

    float4 bb = __ldg(&reinterpret_cast<const float4*>(bias)[lane]);
    float4 r;
    r.x = fmaxf(fmaf(di, acc.x, bb.x), 0.f);
    r.y = fmaxf(fmaf(di, acc.y, bb.y), 0.f);
    r.z = fmaxf(fmaf(di, acc.z, bb.z), 0.f);
    r.w = fmaxf(fmaf(di, acc.w, bb.w), 0.f);
    return r;
}

// Layer 1: write h rows.
__global__ void __launch_bounds__(256)
agg_kernel(const __half* __restrict__ hs, const float* __restrict__ bias,
           float* __restrict__ h) {
    int w = (blockIdx.x * 256 + threadIdx.x) >> 5;
    if (w >= N) return;
    int lane = threadIdx.x & 31;
    float4 r = node_row(reinterpret_cast<const uint2*>(hs), bias, w, lane);
    reinterpret_cast<float4*>(h)[(size_t)w * 32 + lane] = r;
}

// Layer 2 fused with global mean pool: rows never touch memory.
__global__ void __launch_bounds__(256)
agg_pool_kernel(const __half* __restrict__ hs, const float* __restrict__ bias,
                const int* __restrict__ batch) {
    __shared__ float accsm[G * H];
    __shared__ float cntsm[G];
    int tid = threadIdx.x;
    for (int i = tid; i < G * H; i += 256) accsm[i] = 0.f;
    if (tid < G) cntsm[tid] = 0.f;
    __syncthreads();

    int w = (blockIdx.x * 256 + tid) >> 5;      // grid sized so w < N always
    int lane = tid & 31;
    float4 r = node_row(reinterpret_cast<const uint2*>(hs), bias, w, lane);

    int g = __ldg(&batch[w]);
    atomicAdd(&accsm[g * H + lane * 4 + 0], r.x);
    atomicAdd(&accsm[g * H + lane * 4 + 1], r.y);
    atomicAdd(&accsm[g * H + lane * 4 + 2], r.z);
    atomicAdd(&accsm[g * H + lane * 4 + 3], r.w);
    if (lane == 0) atomicAdd(&cntsm[g], 1.0f);
    __syncthreads();

    for (int i = tid; i < G * H; i += 256)
        if (accsm[i] != 0.f) atomicAdd(&g_pool[i], accsm[i]);
    if (tid < G && cntsm[tid] != 0.f) atomicAdd(&g_cntf[tid], cntsm[tid]);
}

// ======================= head =======================

__global__ void head_kernel(const float* __restrict__ Wlin, const float* __restrict__ blin,
                            float* __restrict__ out) {
    int warp = threadIdx.x >> 5, lane = threadIdx.x & 31;
    if (warp >= G * C) return;
    int g = warp >> 1, c = warp & 1;
    float s = 0.f;
    for (int d = lane; d < H; d += 32)
        s += g_pool[g * H + d] * Wlin[d * C + c];
    #pragma unroll
    for (int o = 16; o; o >>= 1) s += __shfl_xor_sync(0xffffffff, s, o);
    if (lane == 0) out[g * C + c] = s / fmaxf(g_cntf[g], 1.0f) + blin[c];
}

} // namespace

extern "C" void kernel_launch(void* const* d_in, const int* in_sizes, int n_in,
                              void* d_out, int out_size) {
    const float* x    = (const float*)d_in[0];
    const int*   ei   = (const int*)  d_in[1];
    const int*   bat  = (const int*)  d_in[2];
    const float* W1   = (const float*)d_in[3];
    const float* b1   = (const float*)d_in[4];
    const float* W2   = (const float*)d_in[5];
    const float* b2   = (const float*)d_in[6];
    const float* Wlin = (const float*)d_in[7];
    const float* blin = (const float*)d_in[8];
    float* out = (float*)d_out;
    const int* src = ei;
    const int* dst = ei + E;

    __half* p_hs;
    float *p_h;
    cudaGetSymbolAddress((void**)&p_hs, g_hs);
    cudaGetSymbolAddress((void**)&p_h,  g_h);

    cudaFuncSetAttribute(gemm_cp<IN>, cudaFuncAttributeMaxDynamicSharedMemorySize, (int)GEMM_SMEM);
    cudaFuncSetAttribute(gemm_cp<H>,  cudaFuncAttributeMaxDynamicSharedMemorySize, (int)GEMM_SMEM);

    static cudaStream_t s2 = nullptr;
    static cudaEvent_t ev_fork = nullptr, ev_join = nullptr;
    if (!s2) {
        cudaStreamCreateWithFlags(&s2, cudaStreamNonBlocking);
        cudaEventCreateWithFlags(&ev_fork, cudaEventDisableTiming);
        cudaEventCreateWithFlags(&ev_join, cudaEventDisableTiming);
    }

    const int gemm_grid = (N + 127) / 128;       // 391
    const int agg_grid  = (N * 32) / 256;        // 6250, exact
    const int nthr_grid = (N + 255) / 256;
    const int e_grid    = (E + 255) / 256;

    // ---- fork: CSR build + pool-zero on side stream, gemm1 on main stream ----
    cudaEventRecord(ev_fork, 0);
    cudaStreamWaitEvent(s2, ev_fork, 0);

    // gemm1 is the 4th enqueued kernel (ncu window index 3).
    count_kernel<<<e_grid, 256, 0, s2>>>(dst);                 // 0
    scanA_kernel<<<NB_SCAN, 256, 0, s2>>>();                   // 1
    scanB_kernel<<<1, 256, 0, s2>>>();                         // 2
    gemm_cp<IN><<<gemm_grid, 256, GEMM_SMEM>>>(x, W1, p_hs);   // 3 (main stream)
    scanCD_kernel<<<nthr_grid, 256, 0, s2>>>();                // 4
    fill_kernel<<<e_grid, 256, 0, s2>>>(src, dst);             // 5
    zero_pool_kernel<<<(G * H + 255) / 256, 256, 0, s2>>>();   // 6
    cudaEventRecord(ev_join, s2);

    // ---- join ----
    cudaStreamWaitEvent(0, ev_join, 0);

    // ---- layer 1 agg, layer 2 (agg fused with pool), head ----
    agg_kernel<<<agg_grid, 256>>>(p_hs, b1, p_h);
    gemm_cp<H><<<gemm_grid, 256, GEMM_SMEM>>>(p_h, W2, p_hs);
    agg_pool_kernel<<<agg_grid, 256>>>(p_hs, b2, bat);
    head_kernel<<<1, G * C * 32>>>(Wlin, blin, out);
}